// round 1
// baseline (speedup 1.0000x reference)
#include <cuda_runtime.h>
#include <math.h>

#define B_  4
#define C_  256
#define D_  128
#define NPOS 6272
#define BM 64
#define BN 64

// ---------------- scratch (static __device__, no allocation) ----------------
__device__ float g_theta[B_ * NPOS * D_];
__device__ float g_phi  [B_ * NPOS * D_];
__device__ float g_gv   [B_ * NPOS * D_];
__device__ float g_y    [B_ * NPOS * D_];

// =============================================================================
// Kernel 1: projections.  out[b][n][d] = sum_c W[d][c] * x[b][c][n]
// grid (N/64, 3, B), 256 threads. which: 0=theta, 1=phi, 2=g
// =============================================================================
__global__ void __launch_bounds__(256) proj_kernel(
    const float* __restrict__ x,
    const float* __restrict__ Wtheta,
    const float* __restrict__ Wphi,
    const float* __restrict__ Wg)
{
    __shared__ float xs[32][64];     // [c-chunk][n]
    __shared__ float wst[32][132];   // [c-chunk][d], transposed W

    const int tid = threadIdx.x;
    const int tx = tid & 15, ty = tid >> 4;
    const int b = blockIdx.z;
    const int which = blockIdx.y;
    const int n0 = blockIdx.x * 64;

    const float* W = (which == 0) ? Wtheta : (which == 1) ? Wphi : Wg;
    float* out = (which == 0) ? g_theta : (which == 1) ? g_phi : g_gv;

    const float* xb = x + (size_t)b * C_ * NPOS;

    float acc[4][8];
#pragma unroll
    for (int i = 0; i < 4; i++)
#pragma unroll
        for (int e = 0; e < 8; e++) acc[i][e] = 0.f;

    for (int c0 = 0; c0 < C_; c0 += 32) {
        __syncthreads();
        // x chunk: [32 c][64 n]
        for (int v = tid; v < 32 * 16; v += 256) {
            int cc = v >> 4, nn = (v & 15) << 2;
            *(float4*)(&xs[cc][nn]) =
                *(const float4*)(xb + (size_t)(c0 + cc) * NPOS + n0 + nn);
        }
        // W chunk transposed: wst[cc][d] = W[d][c0+cc]
        for (int v = tid; v < 128 * 8; v += 256) {
            int d = v >> 3, cc = (v & 7) << 2;
            float4 w = *(const float4*)(W + d * C_ + c0 + cc);
            wst[cc + 0][d] = w.x; wst[cc + 1][d] = w.y;
            wst[cc + 2][d] = w.z; wst[cc + 3][d] = w.w;
        }
        __syncthreads();

#pragma unroll 8
        for (int cc = 0; cc < 32; cc++) {
            float4 xv = *(const float4*)(&xs[cc][4 * ty]);
            float4 wa = *(const float4*)(&wst[cc][4 * tx]);
            float4 wb = *(const float4*)(&wst[cc][64 + 4 * tx]);
            float xr[4] = {xv.x, xv.y, xv.z, xv.w};
#pragma unroll
            for (int i = 0; i < 4; i++) {
                acc[i][0] += xr[i] * wa.x; acc[i][1] += xr[i] * wa.y;
                acc[i][2] += xr[i] * wa.z; acc[i][3] += xr[i] * wa.w;
                acc[i][4] += xr[i] * wb.x; acc[i][5] += xr[i] * wb.y;
                acc[i][6] += xr[i] * wb.z; acc[i][7] += xr[i] * wb.w;
            }
        }
    }

    float* ob = out + ((size_t)b * NPOS + n0) * D_;
#pragma unroll
    for (int i = 0; i < 4; i++) {
        *(float4*)(ob + (4 * ty + i) * D_ + 4 * tx) =
            make_float4(acc[i][0], acc[i][1], acc[i][2], acc[i][3]);
        *(float4*)(ob + (4 * ty + i) * D_ + 64 + 4 * tx) =
            make_float4(acc[i][4], acc[i][5], acc[i][6], acc[i][7]);
    }
}

// =============================================================================
// Kernel 2: flash attention (fp32).  Q=theta [N][D], K=phi, V=g.
// Writes y[b][n][d] = softmax(Q K^T)[n] @ V.
// grid (N/BM, B), 256 threads, dynamic smem.
// Smem tiles use XOR swizzle at float4 granularity: chunk c of row r stored at
// c ^ ((r>>2)&7) so that 16-lane row-strided float4 reads are 2-phase only.
// =============================================================================
#define FLASH_SMEM ((3 * BM * D_ + BM * 68) * 4)

__global__ void __launch_bounds__(256) flash_kernel()
{
    extern __shared__ float sm[];
    float* Qs = sm;                      // 64*128 swizzled
    float* Ks = Qs + BM * D_;            // 64*128 swizzled
    float* Vs = Ks + BN * D_;            // 64*128 swizzled
    float* Ps = Vs + BN * D_;            // 64 x 68 (padded)

    const int tid = threadIdx.x;
    const int tx = tid & 15, ty = tid >> 4;
    const int b = blockIdx.y;
    const int q0 = blockIdx.x * BM;

    const float* Qg = g_theta + ((size_t)b * NPOS + q0) * D_;
    const float* Kg = g_phi + (size_t)b * NPOS * D_;
    const float* Vg = g_gv + (size_t)b * NPOS * D_;

    // load Q tile (swizzled)
    for (int v = tid; v < BM * 32; v += 256) {
        int r = v >> 5, c = v & 31;
        int csw = c ^ ((r >> 2) & 7);
        *(float4*)(Qs + r * D_ + 4 * csw) = *(const float4*)(Qg + r * D_ + 4 * c);
    }

    float Oa[4][4], Ob[4][4], m_i[4], l_i[4];
#pragma unroll
    for (int i = 0; i < 4; i++) {
        m_i[i] = -1e30f; l_i[i] = 0.f;
#pragma unroll
        for (int e = 0; e < 4; e++) { Oa[i][e] = 0.f; Ob[i][e] = 0.f; }
    }

    const int qoff = ty & 7;
    const int koff = tx & 7;

    for (int kt = 0; kt < NPOS / BN; kt++) {
        __syncthreads();   // prev PV done with Vs/Ps; prev S done with Ks
        const float* Kt = Kg + (size_t)kt * BN * D_;
        const float* Vt = Vg + (size_t)kt * BN * D_;
        for (int v = tid; v < BN * 32; v += 256) {
            int r = v >> 5, c = v & 31;
            int csw = c ^ ((r >> 2) & 7);
            *(float4*)(Ks + r * D_ + 4 * csw) = *(const float4*)(Kt + r * D_ + 4 * c);
            *(float4*)(Vs + r * D_ + 4 * csw) = *(const float4*)(Vt + r * D_ + 4 * c);
        }
        __syncthreads();

        // ---- S = Q K^T : s[i][j], rows 4ty+i, cols 4tx+j ----
        float s[4][4];
#pragma unroll
        for (int i = 0; i < 4; i++)
#pragma unroll
            for (int j = 0; j < 4; j++) s[i][j] = 0.f;

#pragma unroll 4
        for (int c = 0; c < 32; c++) {
            float4 q[4], k[4];
#pragma unroll
            for (int i = 0; i < 4; i++)
                q[i] = *(const float4*)(Qs + (4 * ty + i) * D_ + ((c ^ qoff) << 2));
#pragma unroll
            for (int j = 0; j < 4; j++)
                k[j] = *(const float4*)(Ks + (4 * tx + j) * D_ + ((c ^ koff) << 2));
#pragma unroll
            for (int i = 0; i < 4; i++)
#pragma unroll
                for (int j = 0; j < 4; j++)
                    s[i][j] += q[i].x * k[j].x + q[i].y * k[j].y +
                               q[i].z * k[j].z + q[i].w * k[j].w;
        }

        // ---- online softmax (row groups = 16 consecutive lanes, same ty) ----
#pragma unroll
        for (int i = 0; i < 4; i++) {
            float mx = fmaxf(fmaxf(s[i][0], s[i][1]), fmaxf(s[i][2], s[i][3]));
            mx = fmaxf(mx, __shfl_xor_sync(0xffffffffu, mx, 1));
            mx = fmaxf(mx, __shfl_xor_sync(0xffffffffu, mx, 2));
            mx = fmaxf(mx, __shfl_xor_sync(0xffffffffu, mx, 4));
            mx = fmaxf(mx, __shfl_xor_sync(0xffffffffu, mx, 8));
            float mnew = fmaxf(m_i[i], mx);
            float alpha = __expf(m_i[i] - mnew);
            m_i[i] = mnew;
            float rs = 0.f;
#pragma unroll
            for (int j = 0; j < 4; j++) { s[i][j] = __expf(s[i][j] - mnew); rs += s[i][j]; }
            rs += __shfl_xor_sync(0xffffffffu, rs, 1);
            rs += __shfl_xor_sync(0xffffffffu, rs, 2);
            rs += __shfl_xor_sync(0xffffffffu, rs, 4);
            rs += __shfl_xor_sync(0xffffffffu, rs, 8);
            l_i[i] = l_i[i] * alpha + rs;
#pragma unroll
            for (int e = 0; e < 4; e++) { Oa[i][e] *= alpha; Ob[i][e] *= alpha; }
            *(float4*)(Ps + (4 * ty + i) * 68 + 4 * tx) =
                make_float4(s[i][0], s[i][1], s[i][2], s[i][3]);
        }
        __syncthreads();

        // ---- O += P @ V : O rows 4ty+i, cols {4tx..}, {64+4tx..} ----
#pragma unroll 4
        for (int kk = 0; kk < BN; kk += 4) {
            float pr[4][4];
#pragma unroll
            for (int i = 0; i < 4; i++) {
                float4 pv = *(const float4*)(Ps + (4 * ty + i) * 68 + kk);
                pr[i][0] = pv.x; pr[i][1] = pv.y; pr[i][2] = pv.z; pr[i][3] = pv.w;
            }
#pragma unroll
            for (int t = 0; t < 4; t++) {
                int row = kk + t;
                int sw = (row >> 2) & 7;
                float4 va = *(const float4*)(Vs + row * D_ + ((tx ^ sw) << 2));
                float4 vb = *(const float4*)(Vs + row * D_ + (((tx + 16) ^ sw) << 2));
#pragma unroll
                for (int i = 0; i < 4; i++) {
                    float pw = pr[i][t];
                    Oa[i][0] += pw * va.x; Oa[i][1] += pw * va.y;
                    Oa[i][2] += pw * va.z; Oa[i][3] += pw * va.w;
                    Ob[i][0] += pw * vb.x; Ob[i][1] += pw * vb.y;
                    Ob[i][2] += pw * vb.z; Ob[i][3] += pw * vb.w;
                }
            }
        }
    }

    float* Yg = g_y + ((size_t)b * NPOS + q0) * D_;
#pragma unroll
    for (int i = 0; i < 4; i++) {
        float inv = 1.f / l_i[i];
        *(float4*)(Yg + (4 * ty + i) * D_ + 4 * tx) =
            make_float4(Oa[i][0] * inv, Oa[i][1] * inv, Oa[i][2] * inv, Oa[i][3] * inv);
        *(float4*)(Yg + (4 * ty + i) * D_ + 64 + 4 * tx) =
            make_float4(Ob[i][0] * inv, Ob[i][1] * inv, Ob[i][2] * inv, Ob[i][3] * inv);
    }
}

// =============================================================================
// Kernel 3: out[b][c][n] = x[b][c][n] + sum_d Wz[c][d] * y[b][n][d]
// grid (N/64, C/128, B), 256 threads, dynamic smem.
// thread: c rows {4ty+i, 64+4ty+i}, n cols 4tx..4tx+3 (coalesced writes).
// =============================================================================
#define EPI_SMEM ((128 * D_ + 64 * D_) * 4)

__global__ void __launch_bounds__(256) epi_kernel(
    const float* __restrict__ Wz,
    const float* __restrict__ x,
    float* __restrict__ out)
{
    extern __shared__ float sm[];
    float* wzs = sm;             // [128 c][128 d], natural layout
    float* ys  = sm + 128 * D_;  // [64 n][128 d], swizzled

    const int tid = threadIdx.x;
    const int tx = tid & 15, ty = tid >> 4;
    const int b = blockIdx.z;
    const int c0 = blockIdx.y * 128;
    const int n0 = blockIdx.x * 64;

    for (int v = tid; v < 128 * 32; v += 256) {
        int r = v >> 5, c = v & 31;
        *(float4*)(wzs + r * D_ + 4 * c) = *(const float4*)(Wz + (size_t)(c0 + r) * D_ + 4 * c);
    }
    const float* yb = g_y + ((size_t)b * NPOS + n0) * D_;
    for (int v = tid; v < 64 * 32; v += 256) {
        int r = v >> 5, c = v & 31;
        int csw = c ^ ((r >> 2) & 7);
        *(float4*)(ys + r * D_ + 4 * csw) = *(const float4*)(yb + r * D_ + 4 * c);
    }
    __syncthreads();

    float acc[8][4];
#pragma unroll
    for (int i = 0; i < 8; i++)
#pragma unroll
        for (int e = 0; e < 4; e++) acc[i][e] = 0.f;

    const int ysw = tx & 7;
#pragma unroll 4
    for (int d4 = 0; d4 < 32; d4++) {
        float4 yv[4];
#pragma unroll
        for (int e = 0; e < 4; e++)
            yv[e] = *(const float4*)(ys + (4 * tx + e) * D_ + ((d4 ^ ysw) << 2));
#pragma unroll
        for (int i = 0; i < 8; i++) {
            int crow = (i < 4) ? (4 * ty + i) : (64 + 4 * ty + i - 4);
            float4 wv = *(const float4*)(wzs + crow * D_ + 4 * d4);
#pragma unroll
            for (int e = 0; e < 4; e++)
                acc[i][e] += yv[e].x * wv.x + yv[e].y * wv.y +
                             yv[e].z * wv.z + yv[e].w * wv.w;
        }
    }

    const float* xb = x + ((size_t)b * C_ + c0) * NPOS + n0;
    float* ob = out + ((size_t)b * C_ + c0) * NPOS + n0;
#pragma unroll
    for (int i = 0; i < 8; i++) {
        int crow = (i < 4) ? (4 * ty + i) : (64 + 4 * ty + i - 4);
        float4 xr = *(const float4*)(xb + (size_t)crow * NPOS + 4 * tx);
        *(float4*)(ob + (size_t)crow * NPOS + 4 * tx) =
            make_float4(acc[i][0] + xr.x, acc[i][1] + xr.y,
                        acc[i][2] + xr.z, acc[i][3] + xr.w);
    }
}

// =============================================================================
extern "C" void kernel_launch(void* const* d_in, const int* in_sizes, int n_in,
                              void* d_out, int out_size)
{
    const float* x      = (const float*)d_in[0];
    const float* Wg     = (const float*)d_in[1];
    const float* Wtheta = (const float*)d_in[2];
    const float* Wphi   = (const float*)d_in[3];
    const float* Wz     = (const float*)d_in[4];
    float* out = (float*)d_out;

    cudaFuncSetAttribute(flash_kernel, cudaFuncAttributeMaxDynamicSharedMemorySize, FLASH_SMEM);
    cudaFuncSetAttribute(epi_kernel,   cudaFuncAttributeMaxDynamicSharedMemorySize, EPI_SMEM);

    proj_kernel<<<dim3(NPOS / 64, 3, B_), 256>>>(x, Wtheta, Wphi, Wg);
    flash_kernel<<<dim3(NPOS / BM, B_), 256, FLASH_SMEM>>>();
    epi_kernel<<<dim3(NPOS / 64, C_ / 128, B_), 256, EPI_SMEM>>>(Wz, x, out);
}

// round 2
// speedup vs baseline: 1.0592x; 1.0592x over previous
#include <cuda_runtime.h>
#include <math.h>

#define B_  4
#define C_  256
#define D_  128
#define NPOS 6272
#define BM 64
#define BN 64

// ---------------- scratch (static __device__, no allocation) ----------------
__device__ float g_theta[B_ * NPOS * D_];
__device__ float g_phi  [B_ * NPOS * D_];
__device__ float g_gv   [B_ * NPOS * D_];
__device__ float g_y    [B_ * NPOS * D_];

// =============================================================================
// Kernel 1: projections.  out[b][n][d] = sum_c W[d][c] * x[b][c][n]
// grid (N/64, 3, B), 256 threads. which: 0=theta, 1=phi, 2=g
// =============================================================================
__global__ void __launch_bounds__(256) proj_kernel(
    const float* __restrict__ x,
    const float* __restrict__ Wtheta,
    const float* __restrict__ Wphi,
    const float* __restrict__ Wg)
{
    __shared__ float xs[32][64];     // [c-chunk][n]
    __shared__ float wst[32][132];   // [c-chunk][d], transposed W

    const int tid = threadIdx.x;
    const int tx = tid & 15, ty = tid >> 4;
    const int b = blockIdx.z;
    const int which = blockIdx.y;
    const int n0 = blockIdx.x * 64;

    const float* W = (which == 0) ? Wtheta : (which == 1) ? Wphi : Wg;
    float* out = (which == 0) ? g_theta : (which == 1) ? g_phi : g_gv;

    const float* xb = x + (size_t)b * C_ * NPOS;

    float acc[4][8];
#pragma unroll
    for (int i = 0; i < 4; i++)
#pragma unroll
        for (int e = 0; e < 8; e++) acc[i][e] = 0.f;

    for (int c0 = 0; c0 < C_; c0 += 32) {
        __syncthreads();
        // x chunk: [32 c][64 n]
        for (int v = tid; v < 32 * 16; v += 256) {
            int cc = v >> 4, nn = (v & 15) << 2;
            *(float4*)(&xs[cc][nn]) =
                *(const float4*)(xb + (size_t)(c0 + cc) * NPOS + n0 + nn);
        }
        // W chunk transposed: wst[cc][d] = W[d][c0+cc]
        for (int v = tid; v < 128 * 8; v += 256) {
            int d = v >> 3, cc = (v & 7) << 2;
            float4 w = *(const float4*)(W + d * C_ + c0 + cc);
            wst[cc + 0][d] = w.x; wst[cc + 1][d] = w.y;
            wst[cc + 2][d] = w.z; wst[cc + 3][d] = w.w;
        }
        __syncthreads();

#pragma unroll 8
        for (int cc = 0; cc < 32; cc++) {
            float4 xv = *(const float4*)(&xs[cc][4 * ty]);
            float4 wa = *(const float4*)(&wst[cc][4 * tx]);
            float4 wb = *(const float4*)(&wst[cc][64 + 4 * tx]);
            float xr[4] = {xv.x, xv.y, xv.z, xv.w};
#pragma unroll
            for (int i = 0; i < 4; i++) {
                acc[i][0] += xr[i] * wa.x; acc[i][1] += xr[i] * wa.y;
                acc[i][2] += xr[i] * wa.z; acc[i][3] += xr[i] * wa.w;
                acc[i][4] += xr[i] * wb.x; acc[i][5] += xr[i] * wb.y;
                acc[i][6] += xr[i] * wb.z; acc[i][7] += xr[i] * wb.w;
            }
        }
    }

    float* ob = out + ((size_t)b * NPOS + n0) * D_;
#pragma unroll
    for (int i = 0; i < 4; i++) {
        *(float4*)(ob + (4 * ty + i) * D_ + 4 * tx) =
            make_float4(acc[i][0], acc[i][1], acc[i][2], acc[i][3]);
        *(float4*)(ob + (4 * ty + i) * D_ + 64 + 4 * tx) =
            make_float4(acc[i][4], acc[i][5], acc[i][6], acc[i][7]);
    }
}

// =============================================================================
// Kernel 2: flash attention (fp32).  Q=theta [N][D], K=phi, V=g.
// Writes y[b][n][d] = softmax(Q K^T)[n] @ V.
// grid (N/BM, B), 256 threads, dynamic smem.
// Smem tiles use XOR swizzle at float4 granularity: chunk c of row r stored at
// c ^ ((r>>2)&7) so that 16-lane row-strided float4 reads are 2-phase only.
// =============================================================================
#define FLASH_SMEM ((3 * BM * D_ + BM * 68) * 4)

__global__ void __launch_bounds__(256) flash_kernel()
{
    extern __shared__ float sm[];
    float* Qs = sm;                      // 64*128 swizzled
    float* Ks = Qs + BM * D_;            // 64*128 swizzled
    float* Vs = Ks + BN * D_;            // 64*128 swizzled
    float* Ps = Vs + BN * D_;            // 64 x 68 (padded)

    const int tid = threadIdx.x;
    const int tx = tid & 15, ty = tid >> 4;
    const int b = blockIdx.y;
    const int q0 = blockIdx.x * BM;

    const float* Qg = g_theta + ((size_t)b * NPOS + q0) * D_;
    const float* Kg = g_phi + (size_t)b * NPOS * D_;
    const float* Vg = g_gv + (size_t)b * NPOS * D_;

    // load Q tile (swizzled)
    for (int v = tid; v < BM * 32; v += 256) {
        int r = v >> 5, c = v & 31;
        int csw = c ^ ((r >> 2) & 7);
        *(float4*)(Qs + r * D_ + 4 * csw) = *(const float4*)(Qg + r * D_ + 4 * c);
    }

    float Oa[4][4], Ob[4][4], m_i[4], l_i[4];
#pragma unroll
    for (int i = 0; i < 4; i++) {
        m_i[i] = -1e30f; l_i[i] = 0.f;
#pragma unroll
        for (int e = 0; e < 4; e++) { Oa[i][e] = 0.f; Ob[i][e] = 0.f; }
    }

    const int qoff = ty & 7;
    const int koff = tx & 7;

    for (int kt = 0; kt < NPOS / BN; kt++) {
        __syncthreads();   // prev PV done with Vs/Ps; prev S done with Ks
        const float* Kt = Kg + (size_t)kt * BN * D_;
        const float* Vt = Vg + (size_t)kt * BN * D_;
        for (int v = tid; v < BN * 32; v += 256) {
            int r = v >> 5, c = v & 31;
            int csw = c ^ ((r >> 2) & 7);
            *(float4*)(Ks + r * D_ + 4 * csw) = *(const float4*)(Kt + r * D_ + 4 * c);
            *(float4*)(Vs + r * D_ + 4 * csw) = *(const float4*)(Vt + r * D_ + 4 * c);
        }
        __syncthreads();

        // ---- S = Q K^T : s[i][j], rows 4ty+i, cols 4tx+j ----
        float s[4][4];
#pragma unroll
        for (int i = 0; i < 4; i++)
#pragma unroll
            for (int j = 0; j < 4; j++) s[i][j] = 0.f;

#pragma unroll 4
        for (int c = 0; c < 32; c++) {
            float4 q[4], k[4];
#pragma unroll
            for (int i = 0; i < 4; i++)
                q[i] = *(const float4*)(Qs + (4 * ty + i) * D_ + ((c ^ qoff) << 2));
#pragma unroll
            for (int j = 0; j < 4; j++)
                k[j] = *(const float4*)(Ks + (4 * tx + j) * D_ + ((c ^ koff) << 2));
#pragma unroll
            for (int i = 0; i < 4; i++)
#pragma unroll
                for (int j = 0; j < 4; j++)
                    s[i][j] += q[i].x * k[j].x + q[i].y * k[j].y +
                               q[i].z * k[j].z + q[i].w * k[j].w;
        }

        // ---- online softmax (row groups = 16 consecutive lanes, same ty) ----
#pragma unroll
        for (int i = 0; i < 4; i++) {
            float mx = fmaxf(fmaxf(s[i][0], s[i][1]), fmaxf(s[i][2], s[i][3]));
            mx = fmaxf(mx, __shfl_xor_sync(0xffffffffu, mx, 1));
            mx = fmaxf(mx, __shfl_xor_sync(0xffffffffu, mx, 2));
            mx = fmaxf(mx, __shfl_xor_sync(0xffffffffu, mx, 4));
            mx = fmaxf(mx, __shfl_xor_sync(0xffffffffu, mx, 8));
            float mnew = fmaxf(m_i[i], mx);
            float alpha = __expf(m_i[i] - mnew);
            m_i[i] = mnew;
            float rs = 0.f;
#pragma unroll
            for (int j = 0; j < 4; j++) { s[i][j] = __expf(s[i][j] - mnew); rs += s[i][j]; }
            rs += __shfl_xor_sync(0xffffffffu, rs, 1);
            rs += __shfl_xor_sync(0xffffffffu, rs, 2);
            rs += __shfl_xor_sync(0xffffffffu, rs, 4);
            rs += __shfl_xor_sync(0xffffffffu, rs, 8);
            l_i[i] = l_i[i] * alpha + rs;
#pragma unroll
            for (int e = 0; e < 4; e++) { Oa[i][e] *= alpha; Ob[i][e] *= alpha; }
            *(float4*)(Ps + (4 * ty + i) * 68 + 4 * tx) =
                make_float4(s[i][0], s[i][1], s[i][2], s[i][3]);
        }
        __syncthreads();

        // ---- O += P @ V : O rows 4ty+i, cols {4tx..}, {64+4tx..} ----
#pragma unroll 4
        for (int kk = 0; kk < BN; kk += 4) {
            float pr[4][4];
#pragma unroll
            for (int i = 0; i < 4; i++) {
                float4 pv = *(const float4*)(Ps + (4 * ty + i) * 68 + kk);
                pr[i][0] = pv.x; pr[i][1] = pv.y; pr[i][2] = pv.z; pr[i][3] = pv.w;
            }
#pragma unroll
            for (int t = 0; t < 4; t++) {
                int row = kk + t;
                int sw = (row >> 2) & 7;
                float4 va = *(const float4*)(Vs + row * D_ + ((tx ^ sw) << 2));
                float4 vb = *(const float4*)(Vs + row * D_ + (((tx + 16) ^ sw) << 2));
#pragma unroll
                for (int i = 0; i < 4; i++) {
                    float pw = pr[i][t];
                    Oa[i][0] += pw * va.x; Oa[i][1] += pw * va.y;
                    Oa[i][2] += pw * va.z; Oa[i][3] += pw * va.w;
                    Ob[i][0] += pw * vb.x; Ob[i][1] += pw * vb.y;
                    Ob[i][2] += pw * vb.z; Ob[i][3] += pw * vb.w;
                }
            }
        }
    }

    float* Yg = g_y + ((size_t)b * NPOS + q0) * D_;
#pragma unroll
    for (int i = 0; i < 4; i++) {
        float inv = 1.f / l_i[i];
        *(float4*)(Yg + (4 * ty + i) * D_ + 4 * tx) =
            make_float4(Oa[i][0] * inv, Oa[i][1] * inv, Oa[i][2] * inv, Oa[i][3] * inv);
        *(float4*)(Yg + (4 * ty + i) * D_ + 64 + 4 * tx) =
            make_float4(Ob[i][0] * inv, Ob[i][1] * inv, Ob[i][2] * inv, Ob[i][3] * inv);
    }
}

// =============================================================================
// Kernel 3: out[b][c][n] = x[b][c][n] + sum_d Wz[c][d] * y[b][n][d]
// grid (N/64, C/128, B), 256 threads, dynamic smem.
// thread: c rows {4ty+i, 64+4ty+i}, n cols 4tx..4tx+3 (coalesced writes).
// =============================================================================
#define EPI_SMEM ((128 * D_ + 64 * D_) * 4)

__global__ void __launch_bounds__(256) epi_kernel(
    const float* __restrict__ Wz,
    const float* __restrict__ x,
    float* __restrict__ out)
{
    extern __shared__ float sm[];
    float* wzs = sm;             // [128 c][128 d], natural layout
    float* ys  = sm + 128 * D_;  // [64 n][128 d], swizzled

    const int tid = threadIdx.x;
    const int tx = tid & 15, ty = tid >> 4;
    const int b = blockIdx.z;
    const int c0 = blockIdx.y * 128;
    const int n0 = blockIdx.x * 64;

    for (int v = tid; v < 128 * 32; v += 256) {
        int r = v >> 5, c = v & 31;
        *(float4*)(wzs + r * D_ + 4 * c) = *(const float4*)(Wz + (size_t)(c0 + r) * D_ + 4 * c);
    }
    const float* yb = g_y + ((size_t)b * NPOS + n0) * D_;
    for (int v = tid; v < 64 * 32; v += 256) {
        int r = v >> 5, c = v & 31;
        int csw = c ^ ((r >> 2) & 7);
        *(float4*)(ys + r * D_ + 4 * csw) = *(const float4*)(yb + r * D_ + 4 * c);
    }
    __syncthreads();

    float acc[8][4];
#pragma unroll
    for (int i = 0; i < 8; i++)
#pragma unroll
        for (int e = 0; e < 4; e++) acc[i][e] = 0.f;

    const int ysw = tx & 7;
#pragma unroll 4
    for (int d4 = 0; d4 < 32; d4++) {
        float4 yv[4];
#pragma unroll
        for (int e = 0; e < 4; e++)
            yv[e] = *(const float4*)(ys + (4 * tx + e) * D_ + ((d4 ^ ysw) << 2));
#pragma unroll
        for (int i = 0; i < 8; i++) {
            int crow = (i < 4) ? (4 * ty + i) : (64 + 4 * ty + i - 4);
            float4 wv = *(const float4*)(wzs + crow * D_ + 4 * d4);
#pragma unroll
            for (int e = 0; e < 4; e++)
                acc[i][e] += yv[e].x * wv.x + yv[e].y * wv.y +
                             yv[e].z * wv.z + yv[e].w * wv.w;
        }
    }

    const float* xb = x + ((size_t)b * C_ + c0) * NPOS + n0;
    float* ob = out + ((size_t)b * C_ + c0) * NPOS + n0;
#pragma unroll
    for (int i = 0; i < 8; i++) {
        int crow = (i < 4) ? (4 * ty + i) : (64 + 4 * ty + i - 4);
        float4 xr = *(const float4*)(xb + (size_t)crow * NPOS + 4 * tx);
        *(float4*)(ob + (size_t)crow * NPOS + 4 * tx) =
            make_float4(acc[i][0] + xr.x, acc[i][1] + xr.y,
                        acc[i][2] + xr.z, acc[i][3] + xr.w);
    }
}

// =============================================================================
extern "C" void kernel_launch(void* const* d_in, const int* in_sizes, int n_in,
                              void* d_out, int out_size)
{
    const float* x      = (const float*)d_in[0];
    const float* Wg     = (const float*)d_in[1];
    const float* Wtheta = (const float*)d_in[2];
    const float* Wphi   = (const float*)d_in[3];
    const float* Wz     = (const float*)d_in[4];
    float* out = (float*)d_out;

    cudaFuncSetAttribute(flash_kernel, cudaFuncAttributeMaxDynamicSharedMemorySize, FLASH_SMEM);
    cudaFuncSetAttribute(epi_kernel,   cudaFuncAttributeMaxDynamicSharedMemorySize, EPI_SMEM);

    proj_kernel<<<dim3(NPOS / 64, 3, B_), 256>>>(x, Wtheta, Wphi, Wg);
    flash_kernel<<<dim3(NPOS / BM, B_), 256, FLASH_SMEM>>>();
    epi_kernel<<<dim3(NPOS / 64, C_ / 128, B_), 256, EPI_SMEM>>>(Wz, x, out);
}

// round 4
// speedup vs baseline: 3.4202x; 3.2290x over previous
#include <cuda_runtime.h>
#include <cuda_bf16.h>
#include <cstdint>
#include <math.h>

#define B_    4
#define C_    256
#define D_    128
#define NPOS  6272
#define BN    64
#define NSPLIT 2
#define NKT   49            // kv tiles per split (49*2*64 = 6272)
#define MFIX  80.0f

// ---------------- scratch (static __device__, no allocation) ----------------
__device__ __nv_bfloat16 g_qh[(size_t)B_ * NPOS * D_];
__device__ __nv_bfloat16 g_ql[(size_t)B_ * NPOS * D_];
__device__ __nv_bfloat16 g_kh[(size_t)B_ * NPOS * D_];
__device__ __nv_bfloat16 g_kl[(size_t)B_ * NPOS * D_];
__device__ __nv_bfloat16 g_vth[(size_t)B_ * D_ * NPOS];  // V^T [b][d][n]
__device__ __nv_bfloat16 g_vtl[(size_t)B_ * D_ * NPOS];
__device__ float g_yp[NSPLIT][(size_t)B_ * NPOS * D_];   // unnormalized partial O
__device__ float g_lp[NSPLIT][(size_t)B_ * NPOS];        // partial l

// ======================= helpers ==================
__device__ __forceinline__ uint32_t smem_to_u32(const void* p) {
    uint32_t a;
    asm("{ .reg .u64 t; cvta.to.shared.u64 t, %1; cvt.u32.u64 %0, t; }" : "=r"(a) : "l"(p));
    return a;
}
__device__ __forceinline__ void cpa16(uint32_t s, const void* g) {
    asm volatile("cp.async.cg.shared.global [%0], [%1], 16;" :: "r"(s), "l"(g));
}
#define CP_COMMIT() asm volatile("cp.async.commit_group;" ::: "memory")

// D = A(16x16 bf16, row) * B(16x8 bf16, col) + D (f32)
#define MMA16816(c, a, b0_, b1_) \
    asm volatile("mma.sync.aligned.m16n8k16.row.col.f32.bf16.bf16.f32 " \
        "{%0,%1,%2,%3}, {%4,%5,%6,%7}, {%8,%9}, {%0,%1,%2,%3};" \
        : "+f"((c)[0]), "+f"((c)[1]), "+f"((c)[2]), "+f"((c)[3]) \
        : "r"((a)[0]), "r"((a)[1]), "r"((a)[2]), "r"((a)[3]), "r"(b0_), "r"(b1_))

// split f32 pair -> hi(trunc) packed bf16x2 (a in low half) + lo(rn) packed
__device__ __forceinline__ uint32_t packsplit(float a, float b, uint32_t& lo) {
    uint32_t ua = __float_as_uint(a), ub = __float_as_uint(b);
    float r0 = a - __uint_as_float(ua & 0xFFFF0000u);
    float r1 = b - __uint_as_float(ub & 0xFFFF0000u);
    asm("cvt.rn.bf16x2.f32 %0, %1, %2;" : "=r"(lo) : "f"(r1), "f"(r0));
    return (ua >> 16) | (ub & 0xFFFF0000u);
}

// =============================================================================
// Kernel 1: projections -> split bf16.  theta->Q [b][n][d], phi->K [b][n][d],
// g->V^T [b][d][n].  grid (98, 3, B), 256 threads.
// =============================================================================
__global__ void __launch_bounds__(256) proj_kernel(
    const float* __restrict__ x, const float* __restrict__ Wtheta,
    const float* __restrict__ Wphi, const float* __restrict__ Wg)
{
    __shared__ float xs[32][64];
    __shared__ float wst[32][132];
    __shared__ uint16_t tb[128][72];

    const int tid = threadIdx.x;
    const int tx = tid & 15, ty = tid >> 4;
    const int b = blockIdx.z, which = blockIdx.y;
    const int n0 = blockIdx.x * 64;

    const float* W = (which == 0) ? Wtheta : (which == 1) ? Wphi : Wg;
    const float* xb = x + (size_t)b * C_ * NPOS;

    float acc[4][8];
#pragma unroll
    for (int i = 0; i < 4; i++)
#pragma unroll
        for (int e = 0; e < 8; e++) acc[i][e] = 0.f;

    for (int c0 = 0; c0 < C_; c0 += 32) {
        __syncthreads();
        for (int v = tid; v < 32 * 16; v += 256) {
            int cc = v >> 4, nn = (v & 15) << 2;
            *(float4*)(&xs[cc][nn]) = *(const float4*)(xb + (size_t)(c0 + cc) * NPOS + n0 + nn);
        }
        for (int v = tid; v < 128 * 8; v += 256) {
            int d = v >> 3, cc = (v & 7) << 2;
            float4 w = *(const float4*)(W + d * C_ + c0 + cc);
            wst[cc + 0][d] = w.x; wst[cc + 1][d] = w.y;
            wst[cc + 2][d] = w.z; wst[cc + 3][d] = w.w;
        }
        __syncthreads();
#pragma unroll 8
        for (int cc = 0; cc < 32; cc++) {
            float4 xv = *(const float4*)(&xs[cc][4 * ty]);
            float4 wa = *(const float4*)(&wst[cc][4 * tx]);
            float4 wb = *(const float4*)(&wst[cc][64 + 4 * tx]);
            float xr[4] = {xv.x, xv.y, xv.z, xv.w};
#pragma unroll
            for (int i = 0; i < 4; i++) {
                acc[i][0] += xr[i] * wa.x; acc[i][1] += xr[i] * wa.y;
                acc[i][2] += xr[i] * wa.z; acc[i][3] += xr[i] * wa.w;
                acc[i][4] += xr[i] * wb.x; acc[i][5] += xr[i] * wb.y;
                acc[i][6] += xr[i] * wb.z; acc[i][7] += xr[i] * wb.w;
            }
        }
    }

    if (which < 2) {
        uint16_t* hi = (uint16_t*)((which == 0) ? g_qh : g_kh);
        uint16_t* lo = (uint16_t*)((which == 0) ? g_ql : g_kl);
#pragma unroll
        for (int i = 0; i < 4; i++) {
            size_t rb = ((size_t)b * NPOS + n0 + 4 * ty + i) * D_;
            uint32_t l0, l1, l2, l3;
            uint32_t h0 = packsplit(acc[i][0], acc[i][1], l0);
            uint32_t h1 = packsplit(acc[i][2], acc[i][3], l1);
            uint32_t h2 = packsplit(acc[i][4], acc[i][5], l2);
            uint32_t h3 = packsplit(acc[i][6], acc[i][7], l3);
            *(uint2*)(hi + rb + 4 * tx)      = make_uint2(h0, h1);
            *(uint2*)(lo + rb + 4 * tx)      = make_uint2(l0, l1);
            *(uint2*)(hi + rb + 64 + 4 * tx) = make_uint2(h2, h3);
            *(uint2*)(lo + rb + 64 + 4 * tx) = make_uint2(l2, l3);
        }
    } else {
        // hi round (transpose through smem)
        __syncthreads();
#pragma unroll
        for (int i = 0; i < 4; i++)
#pragma unroll
            for (int e = 0; e < 8; e++) {
                int d = (e < 4) ? (4 * tx + e) : (64 + 4 * tx + e - 4);
                tb[d][4 * ty + i] = (uint16_t)(__float_as_uint(acc[i][e]) >> 16);
            }
        __syncthreads();
        for (int v = tid; v < 128 * 8; v += 256) {
            int row = v >> 3, c = v & 7;
            *(uint4*)((uint16_t*)g_vth + ((size_t)(b * D_ + row)) * NPOS + n0 + c * 8) =
                *(uint4*)(&tb[row][c * 8]);
        }
        __syncthreads();
        // lo round
#pragma unroll
        for (int i = 0; i < 4; i++)
#pragma unroll
            for (int e = 0; e < 8; e++) {
                int d = (e < 4) ? (4 * tx + e) : (64 + 4 * tx + e - 4);
                uint32_t u = __float_as_uint(acc[i][e]);
                float res = acc[i][e] - __uint_as_float(u & 0xFFFF0000u);
                __nv_bfloat16 lb = __float2bfloat16(res);
                tb[d][4 * ty + i] = *(uint16_t*)&lb;
            }
        __syncthreads();
        for (int v = tid; v < 128 * 8; v += 256) {
            int row = v >> 3, c = v & 7;
            *(uint4*)((uint16_t*)g_vtl + ((size_t)(b * D_ + row)) * NPOS + n0 + c * 8) =
                *(uint4*)(&tb[row][c * 8]);
        }
    }
}

// =============================================================================
// Kernel 2: flash attention via mma.sync (bf16 3-pass fp32 emulation).
// grid (49, NSPLIT, B), 256 threads (8 warps x 16 q-rows), BM=128, BN=64.
// SMEM: Ql [128][136 bf16] | K stages x2 {hi,lo} [64][136] | V^T x2 {hi,lo} [128][72]
// =============================================================================
#define OFF_QL  0
#define SZ_QL   (128 * 272)
#define OFF_K   SZ_QL
#define SZ_KHL  17408                    // one 64x136 bf16 tile
#define SZ_KST  (2 * SZ_KHL)             // hi+lo per stage
#define OFF_V   (OFF_K + 2 * SZ_KST)
#define SZ_VHL  18432                    // one 128x72 bf16 tile
#define SZ_VST  (2 * SZ_VHL)
#define FLASH_SMEM (OFF_V + 2 * SZ_VST)  // 178176

__device__ __forceinline__ void ld_stage(uint32_t sb, int st, int b, int kt, int tid)
{
    // K hi/lo: 64 rows x 256B (16 chunks), padded stride 272B
    const char* kh = (const char*)(g_kh + ((size_t)b * NPOS + (size_t)kt * BN) * D_);
    const char* kl = (const char*)(g_kl + ((size_t)b * NPOS + (size_t)kt * BN) * D_);
    uint32_t kb = sb + OFF_K + st * SZ_KST;
#pragma unroll
    for (int i = 0; i < 4; i++) {
        int ch = tid + i * 256;
        int r = ch >> 4, c = ch & 15;
        uint32_t off = (uint32_t)(r * 272 + c * 16);
        size_t go = (size_t)r * 256 + c * 16;
        cpa16(kb + off, kh + go);
        cpa16(kb + SZ_KHL + off, kl + go);
    }
    // V^T hi/lo: 128 rows(d) x 128B (8 chunks), padded stride 144B
    const char* vh = (const char*)(g_vth + (size_t)b * D_ * NPOS + (size_t)kt * BN);
    const char* vl = (const char*)(g_vtl + (size_t)b * D_ * NPOS + (size_t)kt * BN);
    uint32_t vb = sb + OFF_V + st * SZ_VST;
#pragma unroll
    for (int i = 0; i < 4; i++) {
        int ch = tid + i * 256;
        int r = ch >> 3, c = ch & 7;
        uint32_t off = (uint32_t)(r * 144 + c * 16);
        size_t go = (size_t)r * (NPOS * 2) + c * 16;
        cpa16(vb + off, vh + go);
        cpa16(vb + SZ_VHL + off, vl + go);
    }
}

__global__ void __launch_bounds__(256, 1) flash_kernel()
{
    extern __shared__ char smem[];
    uint32_t sb = smem_to_u32(smem);
    const int tid = threadIdx.x;
    const int w = tid >> 5, lane = tid & 31;
    const int g = lane >> 2, tq = lane & 3;
    const int q0 = blockIdx.x * 128;
    const int split = blockIdx.y;
    const int b = blockIdx.z;
    const int kb0 = split * NKT;

    // ---- Ql -> smem (padded), prefetch stage 0 and 1 ----
    {
        const char* gq = (const char*)(g_ql + ((size_t)b * NPOS + q0) * D_);
#pragma unroll
        for (int i = 0; i < 8; i++) {
            int ch = tid + i * 256;
            int r = ch >> 4, c = ch & 15;
            cpa16(sb + OFF_QL + r * 272 + c * 16, gq + (size_t)r * 256 + c * 16);
        }
        ld_stage(sb, 0, b, kb0, tid);
    }
    CP_COMMIT();
    ld_stage(sb, 1, b, kb0 + 1, tid);
    CP_COMMIT();

    // ---- Qh fragments (registers, persist across tiles) ----
    uint32_t qh[8][4];
    {
        const uint16_t* gq = (const uint16_t*)(g_qh + ((size_t)b * NPOS + q0 + w * 16) * D_);
#pragma unroll
        for (int kk = 0; kk < 8; kk++) {
            qh[kk][0] = *(const uint32_t*)(gq + (size_t)g * 128 + kk * 16 + 2 * tq);
            qh[kk][1] = *(const uint32_t*)(gq + (size_t)(g + 8) * 128 + kk * 16 + 2 * tq);
            qh[kk][2] = *(const uint32_t*)(gq + (size_t)g * 128 + kk * 16 + 8 + 2 * tq);
            qh[kk][3] = *(const uint32_t*)(gq + (size_t)(g + 8) * 128 + kk * 16 + 8 + 2 * tq);
        }
    }

    float oacc[16][4];
#pragma unroll
    for (int j = 0; j < 16; j++)
#pragma unroll
        for (int e = 0; e < 4; e++) oacc[j][e] = 0.f;
    float lr0 = 0.f, lr1 = 0.f;

    const char* Qls = smem + OFF_QL + (w * 16) * 272;

    for (int t = 0; t < NKT; t++) {
        const int st = t & 1;
        asm volatile("cp.async.wait_group 1;" ::: "memory");
        __syncthreads();

        const char* Kh = smem + OFF_K + st * SZ_KST;
        const char* Kl = Kh + SZ_KHL;
        const char* Vh = smem + OFF_V + st * SZ_VST;
        const char* Vl = Vh + SZ_VHL;

        // ---- S = Qh*Kh + Qh*Kl + Ql*Kh ----
        float sacc[8][4];
#pragma unroll
        for (int j = 0; j < 8; j++)
#pragma unroll
            for (int e = 0; e < 4; e++) sacc[j][e] = 0.f;

#pragma unroll
        for (int p = 0; p < 2; p++) {
            const char* Ks = p ? Kl : Kh;
#pragma unroll
            for (int kk = 0; kk < 8; kk++) {
#pragma unroll
                for (int j = 0; j < 8; j++) {
                    const char* ba = Ks + (j * 8 + g) * 272 + kk * 32 + 4 * tq;
                    uint32_t b0 = *(const uint32_t*)(ba);
                    uint32_t b1 = *(const uint32_t*)(ba + 16);
                    MMA16816(sacc[j], qh[kk], b0, b1);
                }
            }
        }
#pragma unroll
        for (int kk = 0; kk < 8; kk++) {
            uint32_t a[4];
            const char* qa = Qls + g * 272 + kk * 32 + 4 * tq;
            const char* qb = Qls + (g + 8) * 272 + kk * 32 + 4 * tq;
            a[0] = *(const uint32_t*)(qa);
            a[1] = *(const uint32_t*)(qb);
            a[2] = *(const uint32_t*)(qa + 16);
            a[3] = *(const uint32_t*)(qb + 16);
#pragma unroll
            for (int j = 0; j < 8; j++) {
                const char* ba = Kh + (j * 8 + g) * 272 + kk * 32 + 4 * tq;
                uint32_t b0 = *(const uint32_t*)(ba);
                uint32_t b1 = *(const uint32_t*)(ba + 16);
                MMA16816(sacc[j], a, b0, b1);
            }
        }

        // ---- softmax exp(s - MFIX), split P into bf16 hi/lo fragments ----
        uint32_t ph[4][4], pl[4][4];
#pragma unroll
        for (int j = 0; j < 8; j++) {
            float p0 = __expf(sacc[j][0] - MFIX);
            float p1 = __expf(sacc[j][1] - MFIX);
            float p2 = __expf(sacc[j][2] - MFIX);
            float p3 = __expf(sacc[j][3] - MFIX);
            lr0 += p0 + p1;
            lr1 += p2 + p3;
            int kk = j >> 1;
            int hi2 = (j & 1) << 1;   // a-reg pair: 0,1 for even j; 2,3 for odd j
            ph[kk][hi2 + 0] = packsplit(p0, p1, pl[kk][hi2 + 0]);
            ph[kk][hi2 + 1] = packsplit(p2, p3, pl[kk][hi2 + 1]);
        }
        // NOTE: a-reg order is {a0,a1,a2,a3} = {(g,2t),(g+8,2t),(g,2t+8),(g+8,2t+8)}.
        // ph[kk] currently holds {a0,a1} from j=2kk at [0],[1] and {a2,a3} from
        // j=2kk+1 at [2],[3]; but packing above wrote (p0,p1)->row g and (p2,p3)->row g+8.
        // Mapping check: ph[kk][0] = rows g cols 16kk+2t (j=2kk, e0/e1) -> a0 OK
        //                ph[kk][1] = rows g+8 same cols (j=2kk, e2/e3)   -> a1 OK
        //                ph[kk][2] = rows g cols 16kk+8+2t (j=2kk+1)     -> a2 OK
        //                ph[kk][3] = rows g+8                            -> a3 OK

        // ---- O += Ph*Vh + Pl*Vh + Ph*Vl ----
#pragma unroll
        for (int p = 0; p < 3; p++) {
            const char* Vs = (p == 2) ? Vl : Vh;
#pragma unroll
            for (int kk = 0; kk < 4; kk++) {
                const uint32_t* pa = (p == 1) ? pl[kk] : ph[kk];
#pragma unroll
                for (int j = 0; j < 16; j++) {
                    const char* ba = Vs + (j * 8 + g) * 144 + kk * 32 + 4 * tq;
                    uint32_t b0 = *(const uint32_t*)(ba);
                    uint32_t b1 = *(const uint32_t*)(ba + 16);
                    MMA16816(oacc[j], pa, b0, b1);
                }
            }
        }

        __syncthreads();
        if (t + 2 < NKT) ld_stage(sb, st, b, kb0 + t + 2, tid);
        CP_COMMIT();
    }

    // ---- reduce l over the quad (cols), write partials ----
    lr0 += __shfl_xor_sync(0xffffffffu, lr0, 1);
    lr0 += __shfl_xor_sync(0xffffffffu, lr0, 2);
    lr1 += __shfl_xor_sync(0xffffffffu, lr1, 1);
    lr1 += __shfl_xor_sync(0xffffffffu, lr1, 2);
    if (tq == 0) {
        size_t base = (size_t)b * NPOS + q0 + w * 16;
        g_lp[split][base + g] = lr0;
        g_lp[split][base + g + 8] = lr1;
    }

    float* yd = g_yp[split] + ((size_t)b * NPOS + q0 + w * 16) * D_;
#pragma unroll
    for (int j = 0; j < 16; j++) {
        *(float2*)(yd + (size_t)g * D_ + j * 8 + 2 * tq) = make_float2(oacc[j][0], oacc[j][1]);
        *(float2*)(yd + (size_t)(g + 8) * D_ + j * 8 + 2 * tq) = make_float2(oacc[j][2], oacc[j][3]);
    }
}

// =============================================================================
// Kernel 3: out[b][c][n] = x + Wz @ ((y0+y1)/(l0+l1)).  grid (98, 2, 4).
// =============================================================================
#define EPI_SMEM ((128 * D_ + 64 * D_ + 64) * 4)

__global__ void __launch_bounds__(256) epi_kernel(
    const float* __restrict__ Wz, const float* __restrict__ x, float* __restrict__ out)
{
    extern __shared__ float sm[];
    float* wzs = sm;
    float* ys = sm + 128 * D_;
    float* linv = sm + 192 * D_;

    const int tid = threadIdx.x;
    const int tx = tid & 15, ty = tid >> 4;
    const int b = blockIdx.z;
    const int c0 = blockIdx.y * 128;
    const int n0 = blockIdx.x * 64;

    if (tid < 64) {
        size_t li = (size_t)b * NPOS + n0 + tid;
        linv[tid] = 1.f / (g_lp[0][li] + g_lp[1][li]);
    }
    for (int v = tid; v < 128 * 32; v += 256) {
        int rr = v >> 5, c = v & 31;
        *(float4*)(wzs + rr * D_ + 4 * c) = *(const float4*)(Wz + (size_t)(c0 + rr) * D_ + 4 * c);
    }
    __syncthreads();
    const float* y0 = &g_yp[0][((size_t)b * NPOS + n0) * D_];
    const float* y1 = &g_yp[1][((size_t)b * NPOS + n0) * D_];
    for (int v = tid; v < 64 * 32; v += 256) {
        int rr = v >> 5, c = v & 31;
        int csw = c ^ ((rr >> 2) & 7);
        float4 a = *(const float4*)(y0 + rr * D_ + 4 * c);
        float4 bb = *(const float4*)(y1 + rr * D_ + 4 * c);
        float s = linv[rr];
        *(float4*)(ys + rr * D_ + 4 * csw) =
            make_float4((a.x + bb.x) * s, (a.y + bb.y) * s, (a.z + bb.z) * s, (a.w + bb.w) * s);
    }
    __syncthreads();

    float acc[8][4];
#pragma unroll
    for (int i = 0; i < 8; i++)
#pragma unroll
        for (int e = 0; e < 4; e++) acc[i][e] = 0.f;

    const int ysw = tx & 7;
#pragma unroll 4
    for (int d4 = 0; d4 < 32; d4++) {
        float4 yv[4];
#pragma unroll
        for (int e = 0; e < 4; e++)
            yv[e] = *(const float4*)(ys + (4 * tx + e) * D_ + ((d4 ^ ysw) << 2));
#pragma unroll
        for (int i = 0; i < 8; i++) {
            int crow = (i < 4) ? (4 * ty + i) : (64 + 4 * ty + i - 4);
            float4 wv = *(const float4*)(wzs + crow * D_ + 4 * d4);
#pragma unroll
            for (int e = 0; e < 4; e++)
                acc[i][e] += yv[e].x * wv.x + yv[e].y * wv.y + yv[e].z * wv.z + yv[e].w * wv.w;
        }
    }

    const float* xb = x + ((size_t)b * C_ + c0) * NPOS + n0;
    float* ob = out + ((size_t)b * C_ + c0) * NPOS + n0;
#pragma unroll
    for (int i = 0; i < 8; i++) {
        int crow = (i < 4) ? (4 * ty + i) : (64 + 4 * ty + i - 4);
        float4 xr = *(const float4*)(xb + (size_t)crow * NPOS + 4 * tx);
        *(float4*)(ob + (size_t)crow * NPOS + 4 * tx) =
            make_float4(acc[i][0] + xr.x, acc[i][1] + xr.y, acc[i][2] + xr.z, acc[i][3] + xr.w);
    }
}

// =============================================================================
extern "C" void kernel_launch(void* const* d_in, const int* in_sizes, int n_in,
                              void* d_out, int out_size)
{
    const float* x      = (const float*)d_in[0];
    const float* Wg     = (const float*)d_in[1];
    const float* Wtheta = (const float*)d_in[2];
    const float* Wphi   = (const float*)d_in[3];
    const float* Wz     = (const float*)d_in[4];
    float* out = (float*)d_out;

    cudaFuncSetAttribute(flash_kernel, cudaFuncAttributeMaxDynamicSharedMemorySize, FLASH_SMEM);
    cudaFuncSetAttribute(epi_kernel, cudaFuncAttributeMaxDynamicSharedMemorySize, EPI_SMEM);

    proj_kernel<<<dim3(NPOS / 64, 3, B_), 256>>>(x, Wtheta, Wphi, Wg);
    flash_kernel<<<dim3(NPOS / 128, NSPLIT, B_), 256, FLASH_SMEM>>>();
    epi_kernel<<<dim3(NPOS / 64, C_ / 128, B_), 256, EPI_SMEM>>>(Wz, x, out);
}

// round 5
// speedup vs baseline: 3.5860x; 1.0485x over previous
#include <cuda_runtime.h>
#include <cuda_bf16.h>
#include <cstdint>
#include <math.h>

#define B_    4
#define C_    256
#define D_    128
#define NPOS  6272
#define BN    64
#define NSPLIT 2
#define NKT   49            // kv tiles per split (49*2*64 = 6272)
#define MFIX  80.0f

// ---------------- scratch (static __device__, no allocation) ----------------
__device__ __nv_bfloat16 g_qh[(size_t)B_ * NPOS * D_];
__device__ __nv_bfloat16 g_ql[(size_t)B_ * NPOS * D_];
__device__ __nv_bfloat16 g_kh[(size_t)B_ * NPOS * D_];
__device__ __nv_bfloat16 g_kl[(size_t)B_ * NPOS * D_];
__device__ __nv_bfloat16 g_vth[(size_t)B_ * D_ * NPOS];  // V^T [b][d][n]
__device__ __nv_bfloat16 g_vtl[(size_t)B_ * D_ * NPOS];
__device__ float g_yp[NSPLIT][(size_t)B_ * NPOS * D_];   // unnormalized partial O
__device__ float g_lp[NSPLIT][(size_t)B_ * NPOS];        // partial l

// ======================= helpers ==================
__device__ __forceinline__ uint32_t smem_to_u32(const void* p) {
    uint32_t a;
    asm("{ .reg .u64 t; cvta.to.shared.u64 t, %1; cvt.u32.u64 %0, t; }" : "=r"(a) : "l"(p));
    return a;
}
__device__ __forceinline__ void cpa16(uint32_t s, const void* g) {
    asm volatile("cp.async.cg.shared.global [%0], [%1], 16;" :: "r"(s), "l"(g));
}
#define CP_COMMIT() asm volatile("cp.async.commit_group;" ::: "memory")

// D = A(16x16 bf16, row) * B(16x8 bf16, col) + D (f32)
#define MMA16816(c, a, b0_, b1_) \
    asm volatile("mma.sync.aligned.m16n8k16.row.col.f32.bf16.bf16.f32 " \
        "{%0,%1,%2,%3}, {%4,%5,%6,%7}, {%8,%9}, {%0,%1,%2,%3};" \
        : "+f"((c)[0]), "+f"((c)[1]), "+f"((c)[2]), "+f"((c)[3]) \
        : "r"((a)[0]), "r"((a)[1]), "r"((a)[2]), "r"((a)[3]), "r"(b0_), "r"(b1_))

// 4x 8x8 b16 matrices: {b0(j), b1(j), b0(j+1), b1(j+1)}
#define LDMX4(rr, addr) \
    asm volatile("ldmatrix.sync.aligned.m8n8.x4.shared.b16 {%0,%1,%2,%3}, [%4];" \
        : "=r"((rr)[0]), "=r"((rr)[1]), "=r"((rr)[2]), "=r"((rr)[3]) : "r"(addr))

// split f32 pair -> hi(trunc) packed bf16x2 (a in low half) + lo(rn) packed
__device__ __forceinline__ uint32_t packsplit(float a, float b, uint32_t& lo) {
    uint32_t ua = __float_as_uint(a), ub = __float_as_uint(b);
    float r0 = a - __uint_as_float(ua & 0xFFFF0000u);
    float r1 = b - __uint_as_float(ub & 0xFFFF0000u);
    asm("cvt.rn.bf16x2.f32 %0, %1, %2;" : "=r"(lo) : "f"(r1), "f"(r0));
    return (ua >> 16) | (ub & 0xFFFF0000u);
}

// =============================================================================
// Kernel 1: projections -> split bf16.  theta->Q [b][n][d], phi->K [b][n][d],
// g->V^T [b][d][n].  grid (98, 3, B), 256 threads.
// =============================================================================
__global__ void __launch_bounds__(256) proj_kernel(
    const float* __restrict__ x, const float* __restrict__ Wtheta,
    const float* __restrict__ Wphi, const float* __restrict__ Wg)
{
    __shared__ float xs[32][64];
    __shared__ float wst[32][132];
    __shared__ uint16_t tb[128][72];

    const int tid = threadIdx.x;
    const int tx = tid & 15, ty = tid >> 4;
    const int b = blockIdx.z, which = blockIdx.y;
    const int n0 = blockIdx.x * 64;

    const float* W = (which == 0) ? Wtheta : (which == 1) ? Wphi : Wg;
    const float* xb = x + (size_t)b * C_ * NPOS;

    float acc[4][8];
#pragma unroll
    for (int i = 0; i < 4; i++)
#pragma unroll
        for (int e = 0; e < 8; e++) acc[i][e] = 0.f;

    for (int c0 = 0; c0 < C_; c0 += 32) {
        __syncthreads();
        for (int v = tid; v < 32 * 16; v += 256) {
            int cc = v >> 4, nn = (v & 15) << 2;
            *(float4*)(&xs[cc][nn]) = *(const float4*)(xb + (size_t)(c0 + cc) * NPOS + n0 + nn);
        }
        for (int v = tid; v < 128 * 8; v += 256) {
            int d = v >> 3, cc = (v & 7) << 2;
            float4 w = *(const float4*)(W + d * C_ + c0 + cc);
            wst[cc + 0][d] = w.x; wst[cc + 1][d] = w.y;
            wst[cc + 2][d] = w.z; wst[cc + 3][d] = w.w;
        }
        __syncthreads();
#pragma unroll 8
        for (int cc = 0; cc < 32; cc++) {
            float4 xv = *(const float4*)(&xs[cc][4 * ty]);
            float4 wa = *(const float4*)(&wst[cc][4 * tx]);
            float4 wb = *(const float4*)(&wst[cc][64 + 4 * tx]);
            float xr[4] = {xv.x, xv.y, xv.z, xv.w};
#pragma unroll
            for (int i = 0; i < 4; i++) {
                acc[i][0] += xr[i] * wa.x; acc[i][1] += xr[i] * wa.y;
                acc[i][2] += xr[i] * wa.z; acc[i][3] += xr[i] * wa.w;
                acc[i][4] += xr[i] * wb.x; acc[i][5] += xr[i] * wb.y;
                acc[i][6] += xr[i] * wb.z; acc[i][7] += xr[i] * wb.w;
            }
        }
    }

    if (which < 2) {
        uint16_t* hi = (uint16_t*)((which == 0) ? g_qh : g_kh);
        uint16_t* lo = (uint16_t*)((which == 0) ? g_ql : g_kl);
#pragma unroll
        for (int i = 0; i < 4; i++) {
            size_t rb = ((size_t)b * NPOS + n0 + 4 * ty + i) * D_;
            uint32_t l0, l1, l2, l3;
            uint32_t h0 = packsplit(acc[i][0], acc[i][1], l0);
            uint32_t h1 = packsplit(acc[i][2], acc[i][3], l1);
            uint32_t h2 = packsplit(acc[i][4], acc[i][5], l2);
            uint32_t h3 = packsplit(acc[i][6], acc[i][7], l3);
            *(uint2*)(hi + rb + 4 * tx)      = make_uint2(h0, h1);
            *(uint2*)(lo + rb + 4 * tx)      = make_uint2(l0, l1);
            *(uint2*)(hi + rb + 64 + 4 * tx) = make_uint2(h2, h3);
            *(uint2*)(lo + rb + 64 + 4 * tx) = make_uint2(l2, l3);
        }
    } else {
        // hi round (transpose through smem)
        __syncthreads();
#pragma unroll
        for (int i = 0; i < 4; i++)
#pragma unroll
            for (int e = 0; e < 8; e++) {
                int d = (e < 4) ? (4 * tx + e) : (64 + 4 * tx + e - 4);
                tb[d][4 * ty + i] = (uint16_t)(__float_as_uint(acc[i][e]) >> 16);
            }
        __syncthreads();
        for (int v = tid; v < 128 * 8; v += 256) {
            int row = v >> 3, c = v & 7;
            *(uint4*)((uint16_t*)g_vth + ((size_t)(b * D_ + row)) * NPOS + n0 + c * 8) =
                *(uint4*)(&tb[row][c * 8]);
        }
        __syncthreads();
        // lo round
#pragma unroll
        for (int i = 0; i < 4; i++)
#pragma unroll
            for (int e = 0; e < 8; e++) {
                int d = (e < 4) ? (4 * tx + e) : (64 + 4 * tx + e - 4);
                uint32_t u = __float_as_uint(acc[i][e]);
                float res = acc[i][e] - __uint_as_float(u & 0xFFFF0000u);
                __nv_bfloat16 lb = __float2bfloat16(res);
                tb[d][4 * ty + i] = *(uint16_t*)&lb;
            }
        __syncthreads();
        for (int v = tid; v < 128 * 8; v += 256) {
            int row = v >> 3, c = v & 7;
            *(uint4*)((uint16_t*)g_vtl + ((size_t)(b * D_ + row)) * NPOS + n0 + c * 8) =
                *(uint4*)(&tb[row][c * 8]);
        }
    }
}

// =============================================================================
// Kernel 2: flash attention via mma.sync (bf16 3-pass fp32 emulation), with
// pass fusion (each K/V fragment loaded once, reused by 2 MMAs) and ldmatrix.
// Q hi AND lo fragments persist in registers; no Q smem.
// grid (49, NSPLIT, B), 256 threads (8 warps x 16 q-rows), BM=128, BN=64.
// SMEM: K stages x2 {hi,lo} [64][136 bf16] | V^T stages x2 {hi,lo} [128][72]
// =============================================================================
#define SZ_KHL  17408                    // one 64x136 bf16 tile
#define SZ_KST  (2 * SZ_KHL)
#define OFF_V   (2 * SZ_KST)             // 69632
#define SZ_VHL  18432                    // one 128x72 bf16 tile
#define SZ_VST  (2 * SZ_VHL)
#define FLASH_SMEM (OFF_V + 2 * SZ_VST)  // 143360

__device__ __forceinline__ void ld_stage(uint32_t sb, int st, int b, int kt, int tid)
{
    const char* kh = (const char*)(g_kh + ((size_t)b * NPOS + (size_t)kt * BN) * D_);
    const char* kl = (const char*)(g_kl + ((size_t)b * NPOS + (size_t)kt * BN) * D_);
    uint32_t kb = sb + st * SZ_KST;
#pragma unroll
    for (int i = 0; i < 4; i++) {
        int ch = tid + i * 256;
        int r = ch >> 4, c = ch & 15;
        uint32_t off = (uint32_t)(r * 272 + c * 16);
        size_t go = (size_t)r * 256 + c * 16;
        cpa16(kb + off, kh + go);
        cpa16(kb + SZ_KHL + off, kl + go);
    }
    const char* vh = (const char*)(g_vth + (size_t)b * D_ * NPOS + (size_t)kt * BN);
    const char* vl = (const char*)(g_vtl + (size_t)b * D_ * NPOS + (size_t)kt * BN);
    uint32_t vb = sb + OFF_V + st * SZ_VST;
#pragma unroll
    for (int i = 0; i < 4; i++) {
        int ch = tid + i * 256;
        int r = ch >> 3, c = ch & 7;
        uint32_t off = (uint32_t)(r * 144 + c * 16);
        size_t go = (size_t)r * (NPOS * 2) + c * 16;
        cpa16(vb + off, vh + go);
        cpa16(vb + SZ_VHL + off, vl + go);
    }
}

__global__ void __launch_bounds__(256, 1) flash_kernel()
{
    extern __shared__ char smem[];
    uint32_t sb = smem_to_u32(smem);
    const int tid = threadIdx.x;
    const int w = tid >> 5, lane = tid & 31;
    const int g = lane >> 2, tq = lane & 3;
    const int q0 = blockIdx.x * 128;
    const int split = blockIdx.y;
    const int b = blockIdx.z;
    const int kb0 = split * NKT;

    ld_stage(sb, 0, b, kb0, tid);
    CP_COMMIT();
    ld_stage(sb, 1, b, kb0 + 1, tid);
    CP_COMMIT();

    // ---- Q hi+lo fragments (registers, persist across all tiles) ----
    uint32_t qh[8][4], ql[8][4];
    {
        const uint16_t* gh = (const uint16_t*)(g_qh + ((size_t)b * NPOS + q0 + w * 16) * D_);
        const uint16_t* gl = (const uint16_t*)(g_ql + ((size_t)b * NPOS + q0 + w * 16) * D_);
#pragma unroll
        for (int kk = 0; kk < 8; kk++) {
            size_t o0 = (size_t)g * 128 + kk * 16 + 2 * tq;
            size_t o1 = (size_t)(g + 8) * 128 + kk * 16 + 2 * tq;
            qh[kk][0] = *(const uint32_t*)(gh + o0);
            qh[kk][1] = *(const uint32_t*)(gh + o1);
            qh[kk][2] = *(const uint32_t*)(gh + o0 + 8);
            qh[kk][3] = *(const uint32_t*)(gh + o1 + 8);
            ql[kk][0] = *(const uint32_t*)(gl + o0);
            ql[kk][1] = *(const uint32_t*)(gl + o1);
            ql[kk][2] = *(const uint32_t*)(gl + o0 + 8);
            ql[kk][3] = *(const uint32_t*)(gl + o1 + 8);
        }
    }

    float oacc[16][4];
#pragma unroll
    for (int j = 0; j < 16; j++)
#pragma unroll
        for (int e = 0; e < 4; e++) oacc[j][e] = 0.f;
    float lr0 = 0.f, lr1 = 0.f;

    // per-lane ldmatrix row offsets (j-pair layout: lanes 0-15 -> j, 16-31 -> j+1)
    const int r8 = lane & 7, half = (lane >> 3) & 1, jjo = lane >> 4;
    const uint32_t laneK = (uint32_t)((jjo * 8 + r8) * 272 + half * 16);
    const uint32_t laneV = (uint32_t)((jjo * 8 + r8) * 144 + half * 16);

    for (int t = 0; t < NKT; t++) {
        const int st = t & 1;
        asm volatile("cp.async.wait_group 1;" ::: "memory");
        __syncthreads();

        const uint32_t Kh = sb + st * SZ_KST;
        const uint32_t Vh = sb + OFF_V + st * SZ_VST;

        // ---- S = Qh*Kh + Ql*Kh + Qh*Kl  (Kh fragments loaded once) ----
        float sacc[8][4];
#pragma unroll
        for (int j = 0; j < 8; j++)
#pragma unroll
            for (int e = 0; e < 4; e++) sacc[j][e] = 0.f;

#pragma unroll
        for (int kk = 0; kk < 8; kk++) {
#pragma unroll
            for (int jp = 0; jp < 4; jp++) {
                uint32_t addr = Kh + (uint32_t)(jp * (16 * 272) + kk * 32) + laneK;
                uint32_t bh[4], bl[4];
                LDMX4(bh, addr);
                LDMX4(bl, addr + SZ_KHL);
                MMA16816(sacc[2 * jp],     qh[kk], bh[0], bh[1]);
                MMA16816(sacc[2 * jp + 1], qh[kk], bh[2], bh[3]);
                MMA16816(sacc[2 * jp],     ql[kk], bh[0], bh[1]);
                MMA16816(sacc[2 * jp + 1], ql[kk], bh[2], bh[3]);
                MMA16816(sacc[2 * jp],     qh[kk], bl[0], bl[1]);
                MMA16816(sacc[2 * jp + 1], qh[kk], bl[2], bl[3]);
            }
        }

        // ---- softmax exp(s - MFIX), split P into bf16 hi/lo fragments ----
        uint32_t ph[4][4], pl[4][4];
#pragma unroll
        for (int j = 0; j < 8; j++) {
            float p0 = __expf(sacc[j][0] - MFIX);
            float p1 = __expf(sacc[j][1] - MFIX);
            float p2 = __expf(sacc[j][2] - MFIX);
            float p3 = __expf(sacc[j][3] - MFIX);
            lr0 += p0 + p1;
            lr1 += p2 + p3;
            int kk = j >> 1;
            int hi2 = (j & 1) << 1;
            ph[kk][hi2 + 0] = packsplit(p0, p1, pl[kk][hi2 + 0]);
            ph[kk][hi2 + 1] = packsplit(p2, p3, pl[kk][hi2 + 1]);
        }

        // ---- O += Ph*Vh + Pl*Vh + Ph*Vl  (Vh fragments loaded once) ----
#pragma unroll
        for (int kk = 0; kk < 4; kk++) {
#pragma unroll
            for (int jp = 0; jp < 8; jp++) {
                uint32_t addr = Vh + (uint32_t)(jp * (16 * 144) + kk * 32) + laneV;
                uint32_t bh[4], bl[4];
                LDMX4(bh, addr);
                LDMX4(bl, addr + SZ_VHL);
                MMA16816(oacc[2 * jp],     ph[kk], bh[0], bh[1]);
                MMA16816(oacc[2 * jp + 1], ph[kk], bh[2], bh[3]);
                MMA16816(oacc[2 * jp],     pl[kk], bh[0], bh[1]);
                MMA16816(oacc[2 * jp + 1], pl[kk], bh[2], bh[3]);
                MMA16816(oacc[2 * jp],     ph[kk], bl[0], bl[1]);
                MMA16816(oacc[2 * jp + 1], ph[kk], bl[2], bl[3]);
            }
        }

        __syncthreads();
        if (t + 2 < NKT) ld_stage(sb, st, b, kb0 + t + 2, tid);
        CP_COMMIT();
    }

    // ---- reduce l over the quad (cols), write partials ----
    lr0 += __shfl_xor_sync(0xffffffffu, lr0, 1);
    lr0 += __shfl_xor_sync(0xffffffffu, lr0, 2);
    lr1 += __shfl_xor_sync(0xffffffffu, lr1, 1);
    lr1 += __shfl_xor_sync(0xffffffffu, lr1, 2);
    if (tq == 0) {
        size_t base = (size_t)b * NPOS + q0 + w * 16;
        g_lp[split][base + g] = lr0;
        g_lp[split][base + g + 8] = lr1;
    }

    float* yd = g_yp[split] + ((size_t)b * NPOS + q0 + w * 16) * D_;
#pragma unroll
    for (int j = 0; j < 16; j++) {
        *(float2*)(yd + (size_t)g * D_ + j * 8 + 2 * tq) = make_float2(oacc[j][0], oacc[j][1]);
        *(float2*)(yd + (size_t)(g + 8) * D_ + j * 8 + 2 * tq) = make_float2(oacc[j][2], oacc[j][3]);
    }
}

// =============================================================================
// Kernel 3: out[b][c][n] = x + Wz @ ((y0+y1)/(l0+l1)).  grid (98, 2, 4).
// =============================================================================
#define EPI_SMEM ((128 * D_ + 64 * D_ + 64) * 4)

__global__ void __launch_bounds__(256) epi_kernel(
    const float* __restrict__ Wz, const float* __restrict__ x, float* __restrict__ out)
{
    extern __shared__ float sm[];
    float* wzs = sm;
    float* ys = sm + 128 * D_;
    float* linv = sm + 192 * D_;

    const int tid = threadIdx.x;
    const int tx = tid & 15, ty = tid >> 4;
    const int b = blockIdx.z;
    const int c0 = blockIdx.y * 128;
    const int n0 = blockIdx.x * 64;

    if (tid < 64) {
        size_t li = (size_t)b * NPOS + n0 + tid;
        linv[tid] = 1.f / (g_lp[0][li] + g_lp[1][li]);
    }
    for (int v = tid; v < 128 * 32; v += 256) {
        int rr = v >> 5, c = v & 31;
        *(float4*)(wzs + rr * D_ + 4 * c) = *(const float4*)(Wz + (size_t)(c0 + rr) * D_ + 4 * c);
    }
    __syncthreads();
    const float* y0 = &g_yp[0][((size_t)b * NPOS + n0) * D_];
    const float* y1 = &g_yp[1][((size_t)b * NPOS + n0) * D_];
    for (int v = tid; v < 64 * 32; v += 256) {
        int rr = v >> 5, c = v & 31;
        int csw = c ^ ((rr >> 2) & 7);
        float4 a = *(const float4*)(y0 + rr * D_ + 4 * c);
        float4 bb = *(const float4*)(y1 + rr * D_ + 4 * c);
        float s = linv[rr];
        *(float4*)(ys + rr * D_ + 4 * csw) =
            make_float4((a.x + bb.x) * s, (a.y + bb.y) * s, (a.z + bb.z) * s, (a.w + bb.w) * s);
    }
    __syncthreads();

    float acc[8][4];
#pragma unroll
    for (int i = 0; i < 8; i++)
#pragma unroll
        for (int e = 0; e < 4; e++) acc[i][e] = 0.f;

    const int ysw = tx & 7;
#pragma unroll 4
    for (int d4 = 0; d4 < 32; d4++) {
        float4 yv[4];
#pragma unroll
        for (int e = 0; e < 4; e++)
            yv[e] = *(const float4*)(ys + (4 * tx + e) * D_ + ((d4 ^ ysw) << 2));
#pragma unroll
        for (int i = 0; i < 8; i++) {
            int crow = (i < 4) ? (4 * ty + i) : (64 + 4 * ty + i - 4);
            float4 wv = *(const float4*)(wzs + crow * D_ + 4 * d4);
#pragma unroll
            for (int e = 0; e < 4; e++)
                acc[i][e] += yv[e].x * wv.x + yv[e].y * wv.y + yv[e].z * wv.z + yv[e].w * wv.w;
        }
    }

    const float* xb = x + ((size_t)b * C_ + c0) * NPOS + n0;
    float* ob = out + ((size_t)b * C_ + c0) * NPOS + n0;
#pragma unroll
    for (int i = 0; i < 8; i++) {
        int crow = (i < 4) ? (4 * ty + i) : (64 + 4 * ty + i - 4);
        float4 xr = *(const float4*)(xb + (size_t)crow * NPOS + 4 * tx);
        *(float4*)(ob + (size_t)crow * NPOS + 4 * tx) =
            make_float4(acc[i][0] + xr.x, acc[i][1] + xr.y, acc[i][2] + xr.z, acc[i][3] + xr.w);
    }
}

// =============================================================================
extern "C" void kernel_launch(void* const* d_in, const int* in_sizes, int n_in,
                              void* d_out, int out_size)
{
    const float* x      = (const float*)d_in[0];
    const float* Wg     = (const float*)d_in[1];
    const float* Wtheta = (const float*)d_in[2];
    const float* Wphi   = (const float*)d_in[3];
    const float* Wz     = (const float*)d_in[4];
    float* out = (float*)d_out;

    cudaFuncSetAttribute(flash_kernel, cudaFuncAttributeMaxDynamicSharedMemorySize, FLASH_SMEM);
    cudaFuncSetAttribute(epi_kernel, cudaFuncAttributeMaxDynamicSharedMemorySize, EPI_SMEM);

    proj_kernel<<<dim3(NPOS / 64, 3, B_), 256>>>(x, Wtheta, Wphi, Wg);
    flash_kernel<<<dim3(NPOS / 128, NSPLIT, B_), 256, FLASH_SMEM>>>();
    epi_kernel<<<dim3(NPOS / 64, C_ / 128, B_), 256, EPI_SMEM>>>(Wz, x, out);
}

// round 6
// speedup vs baseline: 3.9536x; 1.1025x over previous
#include <cuda_runtime.h>
#include <cuda_bf16.h>
#include <cstdint>
#include <math.h>

#define B_    4
#define C_    256
#define D_    128
#define NPOS  6272
#define BN    64
#define NSPLIT 3
#define MFIX  80.0f

// ---------------- scratch (static __device__, no allocation) ----------------
__device__ __nv_bfloat16 g_qh[(size_t)B_ * NPOS * D_];
__device__ __nv_bfloat16 g_ql[(size_t)B_ * NPOS * D_];
__device__ __nv_bfloat16 g_kh[(size_t)B_ * NPOS * D_];
__device__ __nv_bfloat16 g_kl[(size_t)B_ * NPOS * D_];
__device__ __nv_bfloat16 g_vth[(size_t)B_ * D_ * NPOS];  // V^T [b][d][n]
__device__ __nv_bfloat16 g_vtl[(size_t)B_ * D_ * NPOS];
__device__ float g_yp[NSPLIT][(size_t)B_ * NPOS * D_];   // unnormalized partial O
__device__ float g_lp[NSPLIT][(size_t)B_ * NPOS];        // partial l

// ======================= helpers ==================
__device__ __forceinline__ uint32_t smem_to_u32(const void* p) {
    uint32_t a;
    asm("{ .reg .u64 t; cvta.to.shared.u64 t, %1; cvt.u32.u64 %0, t; }" : "=r"(a) : "l"(p));
    return a;
}
__device__ __forceinline__ void cpa16(uint32_t s, const void* g) {
    asm volatile("cp.async.cg.shared.global [%0], [%1], 16;" :: "r"(s), "l"(g));
}
#define CP_COMMIT() asm volatile("cp.async.commit_group;" ::: "memory")

// D = A(16x16 bf16, row) * B(16x8 bf16, col) + D (f32)
#define MMA16816(c, a, b0_, b1_) \
    asm volatile("mma.sync.aligned.m16n8k16.row.col.f32.bf16.bf16.f32 " \
        "{%0,%1,%2,%3}, {%4,%5,%6,%7}, {%8,%9}, {%0,%1,%2,%3};" \
        : "+f"((c)[0]), "+f"((c)[1]), "+f"((c)[2]), "+f"((c)[3]) \
        : "r"((a)[0]), "r"((a)[1]), "r"((a)[2]), "r"((a)[3]), "r"(b0_), "r"(b1_))

#define LDMX4(rr, addr) \
    asm volatile("ldmatrix.sync.aligned.m8n8.x4.shared.b16 {%0,%1,%2,%3}, [%4];" \
        : "=r"((rr)[0]), "=r"((rr)[1]), "=r"((rr)[2]), "=r"((rr)[3]) : "r"(addr))

// split f32 pair -> hi(trunc) packed bf16x2 (a in low half) + lo(rn) packed
__device__ __forceinline__ uint32_t packsplit(float a, float b, uint32_t& lo) {
    uint32_t ua = __float_as_uint(a), ub = __float_as_uint(b);
    float r0 = a - __uint_as_float(ua & 0xFFFF0000u);
    float r1 = b - __uint_as_float(ub & 0xFFFF0000u);
    asm("cvt.rn.bf16x2.f32 %0, %1, %2;" : "=r"(lo) : "f"(r1), "f"(r0));
    return (ua >> 16) | (ub & 0xFFFF0000u);
}

// =============================================================================
// Kernel 1: projections -> split bf16.  theta->Q [b][n][d], phi->K [b][n][d],
// g->V^T [b][d][n].  grid (98, 3, B), 256 threads.
// =============================================================================
__global__ void __launch_bounds__(256) proj_kernel(
    const float* __restrict__ x, const float* __restrict__ Wtheta,
    const float* __restrict__ Wphi, const float* __restrict__ Wg)
{
    __shared__ float xs[32][64];
    __shared__ float wst[32][132];
    __shared__ uint16_t tb[128][72];

    const int tid = threadIdx.x;
    const int tx = tid & 15, ty = tid >> 4;
    const int b = blockIdx.z, which = blockIdx.y;
    const int n0 = blockIdx.x * 64;

    const float* W = (which == 0) ? Wtheta : (which == 1) ? Wphi : Wg;
    const float* xb = x + (size_t)b * C_ * NPOS;

    float acc[4][8];
#pragma unroll
    for (int i = 0; i < 4; i++)
#pragma unroll
        for (int e = 0; e < 8; e++) acc[i][e] = 0.f;

    for (int c0 = 0; c0 < C_; c0 += 32) {
        __syncthreads();
        for (int v = tid; v < 32 * 16; v += 256) {
            int cc = v >> 4, nn = (v & 15) << 2;
            *(float4*)(&xs[cc][nn]) = *(const float4*)(xb + (size_t)(c0 + cc) * NPOS + n0 + nn);
        }
        for (int v = tid; v < 128 * 8; v += 256) {
            int d = v >> 3, cc = (v & 7) << 2;
            float4 w = *(const float4*)(W + d * C_ + c0 + cc);
            wst[cc + 0][d] = w.x; wst[cc + 1][d] = w.y;
            wst[cc + 2][d] = w.z; wst[cc + 3][d] = w.w;
        }
        __syncthreads();
#pragma unroll 8
        for (int cc = 0; cc < 32; cc++) {
            float4 xv = *(const float4*)(&xs[cc][4 * ty]);
            float4 wa = *(const float4*)(&wst[cc][4 * tx]);
            float4 wb = *(const float4*)(&wst[cc][64 + 4 * tx]);
            float xr[4] = {xv.x, xv.y, xv.z, xv.w};
#pragma unroll
            for (int i = 0; i < 4; i++) {
                acc[i][0] += xr[i] * wa.x; acc[i][1] += xr[i] * wa.y;
                acc[i][2] += xr[i] * wa.z; acc[i][3] += xr[i] * wa.w;
                acc[i][4] += xr[i] * wb.x; acc[i][5] += xr[i] * wb.y;
                acc[i][6] += xr[i] * wb.z; acc[i][7] += xr[i] * wb.w;
            }
        }
    }

    if (which < 2) {
        uint16_t* hi = (uint16_t*)((which == 0) ? g_qh : g_kh);
        uint16_t* lo = (uint16_t*)((which == 0) ? g_ql : g_kl);
#pragma unroll
        for (int i = 0; i < 4; i++) {
            size_t rb = ((size_t)b * NPOS + n0 + 4 * ty + i) * D_;
            uint32_t l0, l1, l2, l3;
            uint32_t h0 = packsplit(acc[i][0], acc[i][1], l0);
            uint32_t h1 = packsplit(acc[i][2], acc[i][3], l1);
            uint32_t h2 = packsplit(acc[i][4], acc[i][5], l2);
            uint32_t h3 = packsplit(acc[i][6], acc[i][7], l3);
            *(uint2*)(hi + rb + 4 * tx)      = make_uint2(h0, h1);
            *(uint2*)(lo + rb + 4 * tx)      = make_uint2(l0, l1);
            *(uint2*)(hi + rb + 64 + 4 * tx) = make_uint2(h2, h3);
            *(uint2*)(lo + rb + 64 + 4 * tx) = make_uint2(l2, l3);
        }
    } else {
        __syncthreads();
#pragma unroll
        for (int i = 0; i < 4; i++)
#pragma unroll
            for (int e = 0; e < 8; e++) {
                int d = (e < 4) ? (4 * tx + e) : (64 + 4 * tx + e - 4);
                tb[d][4 * ty + i] = (uint16_t)(__float_as_uint(acc[i][e]) >> 16);
            }
        __syncthreads();
        for (int v = tid; v < 128 * 8; v += 256) {
            int row = v >> 3, c = v & 7;
            *(uint4*)((uint16_t*)g_vth + ((size_t)(b * D_ + row)) * NPOS + n0 + c * 8) =
                *(uint4*)(&tb[row][c * 8]);
        }
        __syncthreads();
#pragma unroll
        for (int i = 0; i < 4; i++)
#pragma unroll
            for (int e = 0; e < 8; e++) {
                int d = (e < 4) ? (4 * tx + e) : (64 + 4 * tx + e - 4);
                uint32_t u = __float_as_uint(acc[i][e]);
                float res = acc[i][e] - __uint_as_float(u & 0xFFFF0000u);
                __nv_bfloat16 lb = __float2bfloat16(res);
                tb[d][4 * ty + i] = *(uint16_t*)&lb;
            }
        __syncthreads();
        for (int v = tid; v < 128 * 8; v += 256) {
            int row = v >> 3, c = v & 7;
            *(uint4*)((uint16_t*)g_vtl + ((size_t)(b * D_ + row)) * NPOS + n0 + c * 8) =
                *(uint4*)(&tb[row][c * 8]);
        }
    }
}

// =============================================================================
// Kernel 2: flash attention via mma.sync, 3-stage smem pipeline, one sync/tile.
// grid (49, NSPLIT, B), 256 threads (8 warps x 16 q-rows), BM=128, BN=64.
// =============================================================================
#define SZ_KHL  17408                    // one 64x136 bf16 tile
#define SZ_KST  (2 * SZ_KHL)             // 34816
#define OFF_V   (3 * SZ_KST)             // 104448
#define SZ_VHL  18432                    // one 128x72 bf16 tile
#define SZ_VST  (2 * SZ_VHL)             // 36864
#define FLASH_SMEM (OFF_V + 3 * SZ_VST)  // 215040

__device__ __forceinline__ void ld_stage(uint32_t sb, int st, int b, int kt, int tid)
{
    const char* kh = (const char*)(g_kh + ((size_t)b * NPOS + (size_t)kt * BN) * D_);
    const char* kl = (const char*)(g_kl + ((size_t)b * NPOS + (size_t)kt * BN) * D_);
    uint32_t kb = sb + st * SZ_KST;
#pragma unroll
    for (int i = 0; i < 4; i++) {
        int ch = tid + i * 256;
        int r = ch >> 4, c = ch & 15;
        uint32_t off = (uint32_t)(r * 272 + c * 16);
        size_t go = (size_t)r * 256 + c * 16;
        cpa16(kb + off, kh + go);
        cpa16(kb + SZ_KHL + off, kl + go);
    }
    const char* vh = (const char*)(g_vth + (size_t)b * D_ * NPOS + (size_t)kt * BN);
    const char* vl = (const char*)(g_vtl + (size_t)b * D_ * NPOS + (size_t)kt * BN);
    uint32_t vb = sb + OFF_V + st * SZ_VST;
#pragma unroll
    for (int i = 0; i < 4; i++) {
        int ch = tid + i * 256;
        int r = ch >> 3, c = ch & 7;
        uint32_t off = (uint32_t)(r * 144 + c * 16);
        size_t go = (size_t)r * (NPOS * 2) + c * 16;
        cpa16(vb + off, vh + go);
        cpa16(vb + SZ_VHL + off, vl + go);
    }
}

__global__ void __launch_bounds__(256, 1) flash_kernel()
{
    extern __shared__ char smem[];
    uint32_t sb = smem_to_u32(smem);
    const int tid = threadIdx.x;
    const int w = tid >> 5, lane = tid & 31;
    const int g = lane >> 2, tq = lane & 3;
    const int q0 = blockIdx.x * 128;
    const int split = blockIdx.y;
    const int b = blockIdx.z;
    const int ks = (split * 98) / 3;        // 0, 32, 65
    const int ke = ((split + 1) * 98) / 3;  // 32, 65, 98

    ld_stage(sb, 0, b, ks, tid);
    CP_COMMIT();
    ld_stage(sb, 1, b, ks + 1, tid);
    CP_COMMIT();

    // Q hi+lo fragments (registers, persist across all tiles)
    uint32_t qh[8][4], ql[8][4];
    {
        const uint16_t* gh = (const uint16_t*)(g_qh + ((size_t)b * NPOS + q0 + w * 16) * D_);
        const uint16_t* gl = (const uint16_t*)(g_ql + ((size_t)b * NPOS + q0 + w * 16) * D_);
#pragma unroll
        for (int kk = 0; kk < 8; kk++) {
            size_t o0 = (size_t)g * 128 + kk * 16 + 2 * tq;
            size_t o1 = (size_t)(g + 8) * 128 + kk * 16 + 2 * tq;
            qh[kk][0] = *(const uint32_t*)(gh + o0);
            qh[kk][1] = *(const uint32_t*)(gh + o1);
            qh[kk][2] = *(const uint32_t*)(gh + o0 + 8);
            qh[kk][3] = *(const uint32_t*)(gh + o1 + 8);
            ql[kk][0] = *(const uint32_t*)(gl + o0);
            ql[kk][1] = *(const uint32_t*)(gl + o1);
            ql[kk][2] = *(const uint32_t*)(gl + o0 + 8);
            ql[kk][3] = *(const uint32_t*)(gl + o1 + 8);
        }
    }

    float oacc[16][4];
#pragma unroll
    for (int j = 0; j < 16; j++)
#pragma unroll
        for (int e = 0; e < 4; e++) oacc[j][e] = 0.f;
    float lr0 = 0.f, lr1 = 0.f;

    const int r8 = lane & 7, half = (lane >> 3) & 1, jjo = lane >> 4;
    const uint32_t laneK = (uint32_t)((jjo * 8 + r8) * 272 + half * 16);
    const uint32_t laneV = (uint32_t)((jjo * 8 + r8) * 144 + half * 16);

    int st = 0;
    for (int t = ks; t < ke; t++) {
        if (t + 1 < ke) {
            asm volatile("cp.async.wait_group 1;" ::: "memory");
        } else {
            asm volatile("cp.async.wait_group 0;" ::: "memory");
        }
        __syncthreads();
        // prefetch stage t+2 into the buffer not in use (st+2 mod 3)
        if (t + 2 < ke) {
            ld_stage(sb, (st >= 1) ? st - 1 : st + 2, b, t + 2, tid);
            CP_COMMIT();
        }

        const uint32_t Kh = sb + st * SZ_KST;
        const uint32_t Vh = sb + OFF_V + st * SZ_VST;

        // ---- S = Qh*Kh + Ql*Kh + Qh*Kl ----
        float sacc[8][4];
#pragma unroll
        for (int j = 0; j < 8; j++)
#pragma unroll
            for (int e = 0; e < 4; e++) sacc[j][e] = 0.f;

#pragma unroll
        for (int kk = 0; kk < 8; kk++) {
#pragma unroll
            for (int jp = 0; jp < 4; jp++) {
                uint32_t addr = Kh + (uint32_t)(jp * (16 * 272) + kk * 32) + laneK;
                uint32_t bh[4], bl[4];
                LDMX4(bh, addr);
                LDMX4(bl, addr + SZ_KHL);
                MMA16816(sacc[2 * jp],     qh[kk], bh[0], bh[1]);
                MMA16816(sacc[2 * jp + 1], qh[kk], bh[2], bh[3]);
                MMA16816(sacc[2 * jp],     ql[kk], bh[0], bh[1]);
                MMA16816(sacc[2 * jp + 1], ql[kk], bh[2], bh[3]);
                MMA16816(sacc[2 * jp],     qh[kk], bl[0], bl[1]);
                MMA16816(sacc[2 * jp + 1], qh[kk], bl[2], bl[3]);
            }
        }

        // ---- softmax exp(s - MFIX), split P into bf16 hi/lo fragments ----
        uint32_t ph[4][4], pl[4][4];
#pragma unroll
        for (int j = 0; j < 8; j++) {
            float p0 = __expf(sacc[j][0] - MFIX);
            float p1 = __expf(sacc[j][1] - MFIX);
            float p2 = __expf(sacc[j][2] - MFIX);
            float p3 = __expf(sacc[j][3] - MFIX);
            lr0 += p0 + p1;
            lr1 += p2 + p3;
            int kk = j >> 1;
            int hi2 = (j & 1) << 1;
            ph[kk][hi2 + 0] = packsplit(p0, p1, pl[kk][hi2 + 0]);
            ph[kk][hi2 + 1] = packsplit(p2, p3, pl[kk][hi2 + 1]);
        }

        // ---- O += Ph*Vh + Pl*Vh + Ph*Vl ----
#pragma unroll
        for (int kk = 0; kk < 4; kk++) {
#pragma unroll
            for (int jp = 0; jp < 8; jp++) {
                uint32_t addr = Vh + (uint32_t)(jp * (16 * 144) + kk * 32) + laneV;
                uint32_t bh[4], bl[4];
                LDMX4(bh, addr);
                LDMX4(bl, addr + SZ_VHL);
                MMA16816(oacc[2 * jp],     ph[kk], bh[0], bh[1]);
                MMA16816(oacc[2 * jp + 1], ph[kk], bh[2], bh[3]);
                MMA16816(oacc[2 * jp],     pl[kk], bh[0], bh[1]);
                MMA16816(oacc[2 * jp + 1], pl[kk], bh[2], bh[3]);
                MMA16816(oacc[2 * jp],     ph[kk], bl[0], bl[1]);
                MMA16816(oacc[2 * jp + 1], ph[kk], bl[2], bl[3]);
            }
        }

        st = (st == 2) ? 0 : st + 1;
    }

    lr0 += __shfl_xor_sync(0xffffffffu, lr0, 1);
    lr0 += __shfl_xor_sync(0xffffffffu, lr0, 2);
    lr1 += __shfl_xor_sync(0xffffffffu, lr1, 1);
    lr1 += __shfl_xor_sync(0xffffffffu, lr1, 2);
    if (tq == 0) {
        size_t base = (size_t)b * NPOS + q0 + w * 16;
        g_lp[split][base + g] = lr0;
        g_lp[split][base + g + 8] = lr1;
    }

    float* yd = g_yp[split] + ((size_t)b * NPOS + q0 + w * 16) * D_;
#pragma unroll
    for (int j = 0; j < 16; j++) {
        *(float2*)(yd + (size_t)g * D_ + j * 8 + 2 * tq) = make_float2(oacc[j][0], oacc[j][1]);
        *(float2*)(yd + (size_t)(g + 8) * D_ + j * 8 + 2 * tq) = make_float2(oacc[j][2], oacc[j][3]);
    }
}

// =============================================================================
// Kernel 3 (mma): out[b][c][n] = x + Wz @ (Σ_s y_s / L).  The 1/L[n] scale is
// applied to y before the GEMM (linearity).  3-pass bf16 emulation.
// grid (98, 2, 4), 256 threads (8 warps x 16 c-rows), tile 128c x 64n x 128d.
// =============================================================================
#define EPI_WZH  0
#define EPI_WZL  34816
#define EPI_YH   69632
#define EPI_YL   87040
#define EPI_LINV 104448
#define EPI_SMEM (EPI_LINV + 256)

__global__ void __launch_bounds__(256) epi_kernel(
    const float* __restrict__ Wz, const float* __restrict__ x, float* __restrict__ out)
{
    extern __shared__ char smem[];
    uint32_t sb = smem_to_u32(smem);
    const int tid = threadIdx.x;
    const int w = tid >> 5, lane = tid & 31;
    const int g = lane >> 2, tq = lane & 3;
    const int b = blockIdx.z;
    const int c0 = blockIdx.y * 128;
    const int n0 = blockIdx.x * 64;

    float* linv = (float*)(smem + EPI_LINV);
    if (tid < 64) {
        size_t li = (size_t)b * NPOS + n0 + tid;
        linv[tid] = 1.f / (g_lp[0][li] + g_lp[1][li] + g_lp[2][li]);
    }
    __syncthreads();

    // Wz -> split bf16 smem [128][136], stride 272B
    for (int v = tid; v < 128 * 32; v += 256) {
        int r = v >> 5, c = v & 31;
        float4 wv = *(const float4*)(Wz + (size_t)(c0 + r) * D_ + 4 * c);
        uint32_t l0, l1;
        uint32_t h0 = packsplit(wv.x, wv.y, l0);
        uint32_t h1 = packsplit(wv.z, wv.w, l1);
        *(uint2*)(smem + EPI_WZH + r * 272 + c * 8) = make_uint2(h0, h1);
        *(uint2*)(smem + EPI_WZL + r * 272 + c * 8) = make_uint2(l0, l1);
    }
    // y = (y0+y1+y2)*linv[n] -> split bf16 smem [64][136]
    {
        const float* y0 = g_yp[0] + ((size_t)b * NPOS + n0) * D_;
        const float* y1 = g_yp[1] + ((size_t)b * NPOS + n0) * D_;
        const float* y2 = g_yp[2] + ((size_t)b * NPOS + n0) * D_;
        for (int v = tid; v < 64 * 32; v += 256) {
            int r = v >> 5, c = v & 31;
            size_t o = (size_t)r * D_ + 4 * c;
            float4 a = *(const float4*)(y0 + o);
            float4 bb = *(const float4*)(y1 + o);
            float4 cc = *(const float4*)(y2 + o);
            float s = linv[r];
            float vx = (a.x + bb.x + cc.x) * s;
            float vy = (a.y + bb.y + cc.y) * s;
            float vz = (a.z + bb.z + cc.z) * s;
            float vw = (a.w + bb.w + cc.w) * s;
            uint32_t l0, l1;
            uint32_t h0 = packsplit(vx, vy, l0);
            uint32_t h1 = packsplit(vz, vw, l1);
            *(uint2*)(smem + EPI_YH + r * 272 + c * 8) = make_uint2(h0, h1);
            *(uint2*)(smem + EPI_YL + r * 272 + c * 8) = make_uint2(l0, l1);
        }
    }
    __syncthreads();

    float acc[8][4];
#pragma unroll
    for (int j = 0; j < 8; j++)
#pragma unroll
        for (int e = 0; e < 4; e++) acc[j][e] = 0.f;

    const int r8 = lane & 7;
    const uint32_t laneA = (uint32_t)((((lane >> 3) & 1) * 8 + r8) * 272 + (lane >> 4) * 16);
    const uint32_t laneB = (uint32_t)(((lane >> 4) * 8 + r8) * 272 + ((lane >> 3) & 1) * 16);
    const uint32_t wA = sb + EPI_WZH + (uint32_t)(w * 16 * 272);

#pragma unroll
    for (int kk = 0; kk < 8; kk++) {
        uint32_t ah[4], al[4];
        LDMX4(ah, wA + kk * 32 + laneA);
        LDMX4(al, wA + (EPI_WZL - EPI_WZH) + kk * 32 + laneA);
#pragma unroll
        for (int jp = 0; jp < 4; jp++) {
            uint32_t ba = sb + EPI_YH + (uint32_t)(jp * (16 * 272) + kk * 32) + laneB;
            uint32_t bh[4], bl[4];
            LDMX4(bh, ba);
            LDMX4(bl, ba + (EPI_YL - EPI_YH));
            MMA16816(acc[2 * jp],     ah, bh[0], bh[1]);
            MMA16816(acc[2 * jp + 1], ah, bh[2], bh[3]);
            MMA16816(acc[2 * jp],     al, bh[0], bh[1]);
            MMA16816(acc[2 * jp + 1], al, bh[2], bh[3]);
            MMA16816(acc[2 * jp],     ah, bl[0], bl[1]);
            MMA16816(acc[2 * jp + 1], ah, bl[2], bl[3]);
        }
    }

    // epilogue: out = acc + x   (rows c0+w*16+{g,g+8}, cols n0+j*8+2tq)
    const size_t row0 = (size_t)(b * C_ + c0 + w * 16 + g) * NPOS + n0;
    const size_t row1 = row0 + (size_t)8 * NPOS;
#pragma unroll
    for (int j = 0; j < 8; j++) {
        int col = j * 8 + 2 * tq;
        float2 x0 = *(const float2*)(x + row0 + col);
        float2 x1 = *(const float2*)(x + row1 + col);
        *(float2*)(out + row0 + col) = make_float2(acc[j][0] + x0.x, acc[j][1] + x0.y);
        *(float2*)(out + row1 + col) = make_float2(acc[j][2] + x1.x, acc[j][3] + x1.y);
    }
}

// =============================================================================
extern "C" void kernel_launch(void* const* d_in, const int* in_sizes, int n_in,
                              void* d_out, int out_size)
{
    const float* x      = (const float*)d_in[0];
    const float* Wg     = (const float*)d_in[1];
    const float* Wtheta = (const float*)d_in[2];
    const float* Wphi   = (const float*)d_in[3];
    const float* Wz     = (const float*)d_in[4];
    float* out = (float*)d_out;

    cudaFuncSetAttribute(flash_kernel, cudaFuncAttributeMaxDynamicSharedMemorySize, FLASH_SMEM);
    cudaFuncSetAttribute(epi_kernel, cudaFuncAttributeMaxDynamicSharedMemorySize, EPI_SMEM);

    proj_kernel<<<dim3(NPOS / 64, 3, B_), 256>>>(x, Wtheta, Wphi, Wg);
    flash_kernel<<<dim3(NPOS / 128, NSPLIT, B_), 256, FLASH_SMEM>>>();
    epi_kernel<<<dim3(NPOS / 64, C_ / 128, B_), 256, EPI_SMEM>>>(Wz, x, out);
}

// round 7
// speedup vs baseline: 4.3510x; 1.1005x over previous
#include <cuda_runtime.h>
#include <cuda_bf16.h>
#include <cstdint>
#include <math.h>

#define B_    4
#define C_    256
#define D_    128
#define NPOS  6272
#define BN    64
#define NSPLIT 3
#define MFIX  80.0f

// ---------------- scratch (static __device__, no allocation) ----------------
__device__ __nv_bfloat16 g_xh[(size_t)B_ * C_ * NPOS];
__device__ __nv_bfloat16 g_xl[(size_t)B_ * C_ * NPOS];
__device__ __nv_bfloat16 g_wh[3 * D_ * C_];
__device__ __nv_bfloat16 g_wl[3 * D_ * C_];
__device__ __nv_bfloat16 g_qh[(size_t)B_ * NPOS * D_];
__device__ __nv_bfloat16 g_ql[(size_t)B_ * NPOS * D_];
__device__ __nv_bfloat16 g_kh[(size_t)B_ * NPOS * D_];
__device__ __nv_bfloat16 g_kl[(size_t)B_ * NPOS * D_];
__device__ __nv_bfloat16 g_vth[(size_t)B_ * D_ * NPOS];  // V^T [b][d][n]
__device__ __nv_bfloat16 g_vtl[(size_t)B_ * D_ * NPOS];
__device__ float g_yp[NSPLIT][(size_t)B_ * NPOS * D_];   // unnormalized partial O
__device__ float g_lp[NSPLIT][(size_t)B_ * NPOS];        // partial l

// ======================= helpers ==================
__device__ __forceinline__ uint32_t smem_to_u32(const void* p) {
    uint32_t a;
    asm("{ .reg .u64 t; cvta.to.shared.u64 t, %1; cvt.u32.u64 %0, t; }" : "=r"(a) : "l"(p));
    return a;
}
__device__ __forceinline__ void cpa16(uint32_t s, const void* g) {
    asm volatile("cp.async.cg.shared.global [%0], [%1], 16;" :: "r"(s), "l"(g));
}
#define CP_COMMIT() asm volatile("cp.async.commit_group;" ::: "memory")

// D = A(16x16 bf16, row) * B(16x8 bf16, col) + D (f32)
#define MMA16816(c, a, b0_, b1_) \
    asm volatile("mma.sync.aligned.m16n8k16.row.col.f32.bf16.bf16.f32 " \
        "{%0,%1,%2,%3}, {%4,%5,%6,%7}, {%8,%9}, {%0,%1,%2,%3};" \
        : "+f"((c)[0]), "+f"((c)[1]), "+f"((c)[2]), "+f"((c)[3]) \
        : "r"((a)[0]), "r"((a)[1]), "r"((a)[2]), "r"((a)[3]), "r"(b0_), "r"(b1_))

#define LDMX4(rr, addr) \
    asm volatile("ldmatrix.sync.aligned.m8n8.x4.shared.b16 {%0,%1,%2,%3}, [%4];" \
        : "=r"((rr)[0]), "=r"((rr)[1]), "=r"((rr)[2]), "=r"((rr)[3]) : "r"(addr))
#define LDMX4T(rr, addr) \
    asm volatile("ldmatrix.sync.aligned.m8n8.x4.trans.shared.b16 {%0,%1,%2,%3}, [%4];" \
        : "=r"((rr)[0]), "=r"((rr)[1]), "=r"((rr)[2]), "=r"((rr)[3]) : "r"(addr))

// split f32 pair -> hi(trunc) packed bf16x2 (a in low half) + lo(rn) packed
__device__ __forceinline__ uint32_t packsplit(float a, float b, uint32_t& lo) {
    uint32_t ua = __float_as_uint(a), ub = __float_as_uint(b);
    float r0 = a - __uint_as_float(ua & 0xFFFF0000u);
    float r1 = b - __uint_as_float(ub & 0xFFFF0000u);
    asm("cvt.rn.bf16x2.f32 %0, %1, %2;" : "=r"(lo) : "f"(r1), "f"(r0));
    return (ua >> 16) | (ub & 0xFFFF0000u);
}

// =============================================================================
// Kernel 0a: split x -> bf16 hi/lo.  grid 6272, 256 thr (exact cover, float4).
// =============================================================================
__global__ void __launch_bounds__(256) split_x_kernel(const float* __restrict__ x)
{
    size_t i = ((size_t)blockIdx.x * 256 + threadIdx.x) * 4;
    float4 v = *(const float4*)(x + i);
    uint32_t l0, l1;
    uint32_t h0 = packsplit(v.x, v.y, l0);
    uint32_t h1 = packsplit(v.z, v.w, l1);
    *(uint2*)((uint16_t*)g_xh + i) = make_uint2(h0, h1);
    *(uint2*)((uint16_t*)g_xl + i) = make_uint2(l0, l1);
}

// Kernel 0b: split W{theta,phi,g} -> bf16 hi/lo.  grid (32, 3).
__global__ void __launch_bounds__(256) split_w_kernel(
    const float* __restrict__ Wt, const float* __restrict__ Wp,
    const float* __restrict__ Wg_)
{
    int which = blockIdx.y;
    const float* W = (which == 0) ? Wt : (which == 1) ? Wp : Wg_;
    size_t i = ((size_t)blockIdx.x * 256 + threadIdx.x) * 4;
    float4 v = *(const float4*)(W + i);
    uint32_t l0, l1;
    uint32_t h0 = packsplit(v.x, v.y, l0);
    uint32_t h1 = packsplit(v.z, v.w, l1);
    size_t o = (size_t)which * (D_ * C_) + i;
    *(uint2*)((uint16_t*)g_wh + o) = make_uint2(h0, h1);
    *(uint2*)((uint16_t*)g_wl + o) = make_uint2(l0, l1);
}

// =============================================================================
// Kernel 1: proj via mma.sync (3-pass bf16 emulation).
// grid (49, 3, B), 256 thr (8 warps).  which: 0=theta->Q, 1=phi->K, 2=g->V^T.
// Q/K: out[n][d] = x^T @ W^T (A = x^T via ldmatrix.trans, B = W rows).
// V^T: out[d][n] = W @ x (A = W rows, B = x^T via ldmatrix.trans).
// k-chunk = 32 channels, 3-stage cp.async pipeline.
// SMEM stage: XH [32][136] | XL | WH [128][40] | WL   (strides 272B / 80B)
// =============================================================================
#define PSTG 37888
#define PROJ_SMEM (3 * PSTG)   // 113664

__device__ __forceinline__ void proj_ld(uint32_t sb, int s, int b, int which,
                                        int c0, int n0, int tid)
{
    uint32_t st = sb + (uint32_t)s * PSTG;
#pragma unroll
    for (int i = 0; i < 2; i++) {
        int ch = tid + i * 256;
        int r = ch >> 4, c16 = ch & 15;
        size_t src = ((size_t)(b * C_ + c0 + r)) * NPOS + n0 + c16 * 8;
        uint32_t dst = (uint32_t)(r * 272 + c16 * 16);
        cpa16(st + dst, (const char*)g_xh + src * 2);
        cpa16(st + 8704 + dst, (const char*)g_xl + src * 2);
    }
#pragma unroll
    for (int i = 0; i < 2; i++) {
        int ch = tid + i * 256;
        int r = ch >> 2, c16 = ch & 3;
        size_t src = (size_t)which * (D_ * C_) + (size_t)r * C_ + c0 + c16 * 8;
        uint32_t dst = (uint32_t)(r * 80 + c16 * 16);
        cpa16(st + 17408 + dst, (const char*)g_wh + src * 2);
        cpa16(st + 27648 + dst, (const char*)g_wl + src * 2);
    }
}

__global__ void __launch_bounds__(256) proj_mma_kernel()
{
    extern __shared__ char smem[];
    uint32_t sb = smem_to_u32(smem);
    const int tid = threadIdx.x;
    const int w = tid >> 5, lane = tid & 31;
    const int g = lane >> 2, tq = lane & 3;
    const int b = blockIdx.z, which = blockIdx.y;
    const int n0 = blockIdx.x * 128;

    proj_ld(sb, 0, b, which, 0, n0, tid);
    CP_COMMIT();
    proj_ld(sb, 1, b, which, 32, n0, tid);
    CP_COMMIT();

    float acc[16][4];
#pragma unroll
    for (int j = 0; j < 16; j++)
#pragma unroll
        for (int e = 0; e < 4; e++) acc[j][e] = 0.f;

    // lane address components
    const int l7 = lane & 7, lb3 = (lane >> 3) & 1, lb4 = lane >> 4;
    // x^T A-frag (trans): src row c = l7 + lb4*8 (+kk*16), n off = lb3*8 (+w*16)
    const uint32_t laneAX = (uint32_t)((l7 + lb4 * 8) * 272 + (lb3 * 8) * 2);
    // W B-frag (non-trans): row d = lb4*8 + l7 (+jp*16), k-half = lb3*16
    const uint32_t laneBW = (uint32_t)((lb4 * 8 + l7) * 80 + lb3 * 16);
    // W A-frag (non-trans, V path): row d = l7 + lb3*8 (+w*16), k-half = lb4*16
    const uint32_t laneAW = (uint32_t)((l7 + lb3 * 8) * 80 + lb4 * 16);
    // x^T B-frag (trans, V path): src row c = l7 + lb3*8 (+kk*16), n off = lb4*8 (+jp*16)
    const uint32_t laneBX = (uint32_t)((l7 + lb3 * 8) * 272 + (lb4 * 8) * 2);

    int st = 0;
    for (int it = 0; it < 8; it++) {
        if (it + 1 < 8) {
            asm volatile("cp.async.wait_group 1;" ::: "memory");
        } else {
            asm volatile("cp.async.wait_group 0;" ::: "memory");
        }
        __syncthreads();
        if (it + 2 < 8) {
            proj_ld(sb, (st >= 1) ? st - 1 : st + 2, b, which, (it + 2) * 32, n0, tid);
            CP_COMMIT();
        }

        const uint32_t XH = sb + (uint32_t)st * PSTG;
        const uint32_t WH = XH + 17408;

        if (which < 2) {
#pragma unroll
            for (int kk = 0; kk < 2; kk++) {
                uint32_t axh[4], axl[4];
                uint32_t aaddr = XH + (uint32_t)(kk * 16 * 272) + (uint32_t)(w * 16 * 2) + laneAX;
                LDMX4T(axh, aaddr);
                LDMX4T(axl, aaddr + 8704);
#pragma unroll
                for (int jp = 0; jp < 8; jp++) {
                    uint32_t baddr = WH + (uint32_t)(jp * 16 * 80 + kk * 32) + laneBW;
                    uint32_t bh[4], bl[4];
                    LDMX4(bh, baddr);
                    LDMX4(bl, baddr + 10240);
                    MMA16816(acc[2 * jp],     axh, bh[0], bh[1]);
                    MMA16816(acc[2 * jp + 1], axh, bh[2], bh[3]);
                    MMA16816(acc[2 * jp],     axl, bh[0], bh[1]);
                    MMA16816(acc[2 * jp + 1], axl, bh[2], bh[3]);
                    MMA16816(acc[2 * jp],     axh, bl[0], bl[1]);
                    MMA16816(acc[2 * jp + 1], axh, bl[2], bl[3]);
                }
            }
        } else {
#pragma unroll
            for (int kk = 0; kk < 2; kk++) {
                uint32_t awh[4], awl[4];
                uint32_t aaddr = WH + (uint32_t)(w * 16 * 80 + kk * 32) + laneAW;
                LDMX4(awh, aaddr);
                LDMX4(awl, aaddr + 10240);
#pragma unroll
                for (int jp = 0; jp < 8; jp++) {
                    uint32_t baddr = XH + (uint32_t)(kk * 16 * 272) + (uint32_t)(jp * 16 * 2) + laneBX;
                    uint32_t bxh[4], bxl[4];
                    LDMX4T(bxh, baddr);
                    LDMX4T(bxl, baddr + 8704);
                    MMA16816(acc[2 * jp],     awh, bxh[0], bxh[1]);
                    MMA16816(acc[2 * jp + 1], awh, bxh[2], bxh[3]);
                    MMA16816(acc[2 * jp],     awl, bxh[0], bxh[1]);
                    MMA16816(acc[2 * jp + 1], awl, bxh[2], bxh[3]);
                    MMA16816(acc[2 * jp],     awh, bxl[0], bxl[1]);
                    MMA16816(acc[2 * jp + 1], awh, bxl[2], bxl[3]);
                }
            }
        }
        st = (st == 2) ? 0 : st + 1;
    }

    if (which < 2) {
        uint16_t* hi = (uint16_t*)((which == 0) ? g_qh : g_kh);
        uint16_t* lo = (uint16_t*)((which == 0) ? g_ql : g_kl);
        size_t row0 = ((size_t)b * NPOS + n0 + w * 16 + g) * D_;
        size_t row1 = row0 + (size_t)8 * D_;
#pragma unroll
        for (int j = 0; j < 16; j++) {
            int col = j * 8 + 2 * tq;
            uint32_t lo0, lo1;
            uint32_t h0 = packsplit(acc[j][0], acc[j][1], lo0);
            uint32_t h1 = packsplit(acc[j][2], acc[j][3], lo1);
            *(uint32_t*)(hi + row0 + col) = h0;
            *(uint32_t*)(lo + row0 + col) = lo0;
            *(uint32_t*)(hi + row1 + col) = h1;
            *(uint32_t*)(lo + row1 + col) = lo1;
        }
    } else {
        uint16_t* hi = (uint16_t*)g_vth;
        uint16_t* lo = (uint16_t*)g_vtl;
        size_t row0 = ((size_t)b * D_ + w * 16 + g) * NPOS + n0;
        size_t row1 = row0 + (size_t)8 * NPOS;
#pragma unroll
        for (int j = 0; j < 16; j++) {
            int col = j * 8 + 2 * tq;
            uint32_t lo0, lo1;
            uint32_t h0 = packsplit(acc[j][0], acc[j][1], lo0);
            uint32_t h1 = packsplit(acc[j][2], acc[j][3], lo1);
            *(uint32_t*)(hi + row0 + col) = h0;
            *(uint32_t*)(lo + row0 + col) = lo0;
            *(uint32_t*)(hi + row1 + col) = h1;
            *(uint32_t*)(lo + row1 + col) = lo1;
        }
    }
}

// =============================================================================
// Kernel 2: flash attention via mma.sync, 3-stage smem pipeline, one sync/tile.
// grid (49, NSPLIT, B), 256 threads (8 warps x 16 q-rows), BM=128, BN=64.
// =============================================================================
#define SZ_KHL  17408                    // one 64x136 bf16 tile
#define SZ_KST  (2 * SZ_KHL)             // 34816
#define OFF_V   (3 * SZ_KST)             // 104448
#define SZ_VHL  18432                    // one 128x72 bf16 tile
#define SZ_VST  (2 * SZ_VHL)             // 36864
#define FLASH_SMEM (OFF_V + 3 * SZ_VST)  // 215040

__device__ __forceinline__ void ld_stage(uint32_t sb, int st, int b, int kt, int tid)
{
    const char* kh = (const char*)(g_kh + ((size_t)b * NPOS + (size_t)kt * BN) * D_);
    const char* kl = (const char*)(g_kl + ((size_t)b * NPOS + (size_t)kt * BN) * D_);
    uint32_t kb = sb + st * SZ_KST;
#pragma unroll
    for (int i = 0; i < 4; i++) {
        int ch = tid + i * 256;
        int r = ch >> 4, c = ch & 15;
        uint32_t off = (uint32_t)(r * 272 + c * 16);
        size_t go = (size_t)r * 256 + c * 16;
        cpa16(kb + off, kh + go);
        cpa16(kb + SZ_KHL + off, kl + go);
    }
    const char* vh = (const char*)(g_vth + (size_t)b * D_ * NPOS + (size_t)kt * BN);
    const char* vl = (const char*)(g_vtl + (size_t)b * D_ * NPOS + (size_t)kt * BN);
    uint32_t vb = sb + OFF_V + st * SZ_VST;
#pragma unroll
    for (int i = 0; i < 4; i++) {
        int ch = tid + i * 256;
        int r = ch >> 3, c = ch & 7;
        uint32_t off = (uint32_t)(r * 144 + c * 16);
        size_t go = (size_t)r * (NPOS * 2) + c * 16;
        cpa16(vb + off, vh + go);
        cpa16(vb + SZ_VHL + off, vl + go);
    }
}

__global__ void __launch_bounds__(256, 1) flash_kernel()
{
    extern __shared__ char smem[];
    uint32_t sb = smem_to_u32(smem);
    const int tid = threadIdx.x;
    const int w = tid >> 5, lane = tid & 31;
    const int g = lane >> 2, tq = lane & 3;
    const int q0 = blockIdx.x * 128;
    const int split = blockIdx.y;
    const int b = blockIdx.z;
    const int ks = (split * 98) / 3;
    const int ke = ((split + 1) * 98) / 3;

    ld_stage(sb, 0, b, ks, tid);
    CP_COMMIT();
    ld_stage(sb, 1, b, ks + 1, tid);
    CP_COMMIT();

    uint32_t qh[8][4], ql[8][4];
    {
        const uint16_t* gh = (const uint16_t*)(g_qh + ((size_t)b * NPOS + q0 + w * 16) * D_);
        const uint16_t* gl = (const uint16_t*)(g_ql + ((size_t)b * NPOS + q0 + w * 16) * D_);
#pragma unroll
        for (int kk = 0; kk < 8; kk++) {
            size_t o0 = (size_t)g * 128 + kk * 16 + 2 * tq;
            size_t o1 = (size_t)(g + 8) * 128 + kk * 16 + 2 * tq;
            qh[kk][0] = *(const uint32_t*)(gh + o0);
            qh[kk][1] = *(const uint32_t*)(gh + o1);
            qh[kk][2] = *(const uint32_t*)(gh + o0 + 8);
            qh[kk][3] = *(const uint32_t*)(gh + o1 + 8);
            ql[kk][0] = *(const uint32_t*)(gl + o0);
            ql[kk][1] = *(const uint32_t*)(gl + o1);
            ql[kk][2] = *(const uint32_t*)(gl + o0 + 8);
            ql[kk][3] = *(const uint32_t*)(gl + o1 + 8);
        }
    }

    float oacc[16][4];
#pragma unroll
    for (int j = 0; j < 16; j++)
#pragma unroll
        for (int e = 0; e < 4; e++) oacc[j][e] = 0.f;
    float lr0 = 0.f, lr1 = 0.f;

    const int r8 = lane & 7, half = (lane >> 3) & 1, jjo = lane >> 4;
    const uint32_t laneK = (uint32_t)((jjo * 8 + r8) * 272 + half * 16);
    const uint32_t laneV = (uint32_t)((jjo * 8 + r8) * 144 + half * 16);

    int st = 0;
    for (int t = ks; t < ke; t++) {
        if (t + 1 < ke) {
            asm volatile("cp.async.wait_group 1;" ::: "memory");
        } else {
            asm volatile("cp.async.wait_group 0;" ::: "memory");
        }
        __syncthreads();
        if (t + 2 < ke) {
            ld_stage(sb, (st >= 1) ? st - 1 : st + 2, b, t + 2, tid);
            CP_COMMIT();
        }

        const uint32_t Kh = sb + st * SZ_KST;
        const uint32_t Vh = sb + OFF_V + st * SZ_VST;

        float sacc[8][4];
#pragma unroll
        for (int j = 0; j < 8; j++)
#pragma unroll
            for (int e = 0; e < 4; e++) sacc[j][e] = 0.f;

#pragma unroll
        for (int kk = 0; kk < 8; kk++) {
#pragma unroll
            for (int jp = 0; jp < 4; jp++) {
                uint32_t addr = Kh + (uint32_t)(jp * (16 * 272) + kk * 32) + laneK;
                uint32_t bh[4], bl[4];
                LDMX4(bh, addr);
                LDMX4(bl, addr + SZ_KHL);
                MMA16816(sacc[2 * jp],     qh[kk], bh[0], bh[1]);
                MMA16816(sacc[2 * jp + 1], qh[kk], bh[2], bh[3]);
                MMA16816(sacc[2 * jp],     ql[kk], bh[0], bh[1]);
                MMA16816(sacc[2 * jp + 1], ql[kk], bh[2], bh[3]);
                MMA16816(sacc[2 * jp],     qh[kk], bl[0], bl[1]);
                MMA16816(sacc[2 * jp + 1], qh[kk], bl[2], bl[3]);
            }
        }

        uint32_t ph[4][4], pl[4][4];
#pragma unroll
        for (int j = 0; j < 8; j++) {
            float p0 = __expf(sacc[j][0] - MFIX);
            float p1 = __expf(sacc[j][1] - MFIX);
            float p2 = __expf(sacc[j][2] - MFIX);
            float p3 = __expf(sacc[j][3] - MFIX);
            lr0 += p0 + p1;
            lr1 += p2 + p3;
            int kk = j >> 1;
            int hi2 = (j & 1) << 1;
            ph[kk][hi2 + 0] = packsplit(p0, p1, pl[kk][hi2 + 0]);
            ph[kk][hi2 + 1] = packsplit(p2, p3, pl[kk][hi2 + 1]);
        }

#pragma unroll
        for (int kk = 0; kk < 4; kk++) {
#pragma unroll
            for (int jp = 0; jp < 8; jp++) {
                uint32_t addr = Vh + (uint32_t)(jp * (16 * 144) + kk * 32) + laneV;
                uint32_t bh[4], bl[4];
                LDMX4(bh, addr);
                LDMX4(bl, addr + SZ_VHL);
                MMA16816(oacc[2 * jp],     ph[kk], bh[0], bh[1]);
                MMA16816(oacc[2 * jp + 1], ph[kk], bh[2], bh[3]);
                MMA16816(oacc[2 * jp],     pl[kk], bh[0], bh[1]);
                MMA16816(oacc[2 * jp + 1], pl[kk], bh[2], bh[3]);
                MMA16816(oacc[2 * jp],     ph[kk], bl[0], bl[1]);
                MMA16816(oacc[2 * jp + 1], ph[kk], bl[2], bl[3]);
            }
        }

        st = (st == 2) ? 0 : st + 1;
    }

    lr0 += __shfl_xor_sync(0xffffffffu, lr0, 1);
    lr0 += __shfl_xor_sync(0xffffffffu, lr0, 2);
    lr1 += __shfl_xor_sync(0xffffffffu, lr1, 1);
    lr1 += __shfl_xor_sync(0xffffffffu, lr1, 2);
    if (tq == 0) {
        size_t base = (size_t)b * NPOS + q0 + w * 16;
        g_lp[split][base + g] = lr0;
        g_lp[split][base + g + 8] = lr1;
    }

    float* yd = g_yp[split] + ((size_t)b * NPOS + q0 + w * 16) * D_;
#pragma unroll
    for (int j = 0; j < 16; j++) {
        *(float2*)(yd + (size_t)g * D_ + j * 8 + 2 * tq) = make_float2(oacc[j][0], oacc[j][1]);
        *(float2*)(yd + (size_t)(g + 8) * D_ + j * 8 + 2 * tq) = make_float2(oacc[j][2], oacc[j][3]);
    }
}

// =============================================================================
// Kernel 3 (mma): out[b][c][n] = x + Wz @ (Σ_s y_s / L).
// =============================================================================
#define EPI_WZH  0
#define EPI_WZL  34816
#define EPI_YH   69632
#define EPI_YL   87040
#define EPI_LINV 104448
#define EPI_SMEM (EPI_LINV + 256)

__global__ void __launch_bounds__(256) epi_kernel(
    const float* __restrict__ Wz, const float* __restrict__ x, float* __restrict__ out)
{
    extern __shared__ char smem[];
    uint32_t sb = smem_to_u32(smem);
    const int tid = threadIdx.x;
    const int w = tid >> 5, lane = tid & 31;
    const int g = lane >> 2, tq = lane & 3;
    const int b = blockIdx.z;
    const int c0 = blockIdx.y * 128;
    const int n0 = blockIdx.x * 64;

    float* linv = (float*)(smem + EPI_LINV);
    if (tid < 64) {
        size_t li = (size_t)b * NPOS + n0 + tid;
        linv[tid] = 1.f / (g_lp[0][li] + g_lp[1][li] + g_lp[2][li]);
    }
    __syncthreads();

    for (int v = tid; v < 128 * 32; v += 256) {
        int r = v >> 5, c = v & 31;
        float4 wv = *(const float4*)(Wz + (size_t)(c0 + r) * D_ + 4 * c);
        uint32_t l0, l1;
        uint32_t h0 = packsplit(wv.x, wv.y, l0);
        uint32_t h1 = packsplit(wv.z, wv.w, l1);
        *(uint2*)(smem + EPI_WZH + r * 272 + c * 8) = make_uint2(h0, h1);
        *(uint2*)(smem + EPI_WZL + r * 272 + c * 8) = make_uint2(l0, l1);
    }
    {
        const float* y0 = g_yp[0] + ((size_t)b * NPOS + n0) * D_;
        const float* y1 = g_yp[1] + ((size_t)b * NPOS + n0) * D_;
        const float* y2 = g_yp[2] + ((size_t)b * NPOS + n0) * D_;
        for (int v = tid; v < 64 * 32; v += 256) {
            int r = v >> 5, c = v & 31;
            size_t o = (size_t)r * D_ + 4 * c;
            float4 a = *(const float4*)(y0 + o);
            float4 bb = *(const float4*)(y1 + o);
            float4 cc = *(const float4*)(y2 + o);
            float s = linv[r];
            float vx = (a.x + bb.x + cc.x) * s;
            float vy = (a.y + bb.y + cc.y) * s;
            float vz = (a.z + bb.z + cc.z) * s;
            float vw = (a.w + bb.w + cc.w) * s;
            uint32_t l0, l1;
            uint32_t h0 = packsplit(vx, vy, l0);
            uint32_t h1 = packsplit(vz, vw, l1);
            *(uint2*)(smem + EPI_YH + r * 272 + c * 8) = make_uint2(h0, h1);
            *(uint2*)(smem + EPI_YL + r * 272 + c * 8) = make_uint2(l0, l1);
        }
    }
    __syncthreads();

    float acc[8][4];
#pragma unroll
    for (int j = 0; j < 8; j++)
#pragma unroll
        for (int e = 0; e < 4; e++) acc[j][e] = 0.f;

    const int r8 = lane & 7;
    const uint32_t laneA = (uint32_t)((((lane >> 3) & 1) * 8 + r8) * 272 + (lane >> 4) * 16);
    const uint32_t laneB = (uint32_t)(((lane >> 4) * 8 + r8) * 272 + ((lane >> 3) & 1) * 16);
    const uint32_t wA = sb + EPI_WZH + (uint32_t)(w * 16 * 272);

#pragma unroll
    for (int kk = 0; kk < 8; kk++) {
        uint32_t ah[4], al[4];
        LDMX4(ah, wA + kk * 32 + laneA);
        LDMX4(al, wA + (EPI_WZL - EPI_WZH) + kk * 32 + laneA);
#pragma unroll
        for (int jp = 0; jp < 4; jp++) {
            uint32_t ba = sb + EPI_YH + (uint32_t)(jp * (16 * 272) + kk * 32) + laneB;
            uint32_t bh[4], bl[4];
            LDMX4(bh, ba);
            LDMX4(bl, ba + (EPI_YL - EPI_YH));
            MMA16816(acc[2 * jp],     ah, bh[0], bh[1]);
            MMA16816(acc[2 * jp + 1], ah, bh[2], bh[3]);
            MMA16816(acc[2 * jp],     al, bh[0], bh[1]);
            MMA16816(acc[2 * jp + 1], al, bh[2], bh[3]);
            MMA16816(acc[2 * jp],     ah, bl[0], bl[1]);
            MMA16816(acc[2 * jp + 1], ah, bl[2], bl[3]);
        }
    }

    const size_t row0 = (size_t)(b * C_ + c0 + w * 16 + g) * NPOS + n0;
    const size_t row1 = row0 + (size_t)8 * NPOS;
#pragma unroll
    for (int j = 0; j < 8; j++) {
        int col = j * 8 + 2 * tq;
        float2 x0 = *(const float2*)(x + row0 + col);
        float2 x1 = *(const float2*)(x + row1 + col);
        *(float2*)(out + row0 + col) = make_float2(acc[j][0] + x0.x, acc[j][1] + x0.y);
        *(float2*)(out + row1 + col) = make_float2(acc[j][2] + x1.x, acc[j][3] + x1.y);
    }
}

// =============================================================================
extern "C" void kernel_launch(void* const* d_in, const int* in_sizes, int n_in,
                              void* d_out, int out_size)
{
    const float* x      = (const float*)d_in[0];
    const float* Wg     = (const float*)d_in[1];
    const float* Wtheta = (const float*)d_in[2];
    const float* Wphi   = (const float*)d_in[3];
    const float* Wz     = (const float*)d_in[4];
    float* out = (float*)d_out;

    cudaFuncSetAttribute(proj_mma_kernel, cudaFuncAttributeMaxDynamicSharedMemorySize, PROJ_SMEM);
    cudaFuncSetAttribute(flash_kernel, cudaFuncAttributeMaxDynamicSharedMemorySize, FLASH_SMEM);
    cudaFuncSetAttribute(epi_kernel, cudaFuncAttributeMaxDynamicSharedMemorySize, EPI_SMEM);

    split_x_kernel<<<6272, 256>>>(x);
    split_w_kernel<<<dim3(32, 3), 256>>>(Wtheta, Wphi, Wg);
    proj_mma_kernel<<<dim3(NPOS / 128, 3, B_), 256, PROJ_SMEM>>>();
    flash_kernel<<<dim3(NPOS / 128, NSPLIT, B_), 256, FLASH_SMEM>>>();
    epi_kernel<<<dim3(NPOS / 64, C_ / 128, B_), 256, EPI_SMEM>>>(Wz, x, out);
}

// round 8
// speedup vs baseline: 4.3576x; 1.0015x over previous
#include <cuda_runtime.h>
#include <cuda_bf16.h>
#include <cstdint>
#include <math.h>

#define B_    4
#define C_    256
#define D_    128
#define NPOS  6272
#define BN    64
#define NSPLIT 3
#define MFIX  80.0f

// ---------------- scratch (static __device__, no allocation) ----------------
__device__ __nv_bfloat16 g_xh[(size_t)B_ * C_ * NPOS];
__device__ __nv_bfloat16 g_xl[(size_t)B_ * C_ * NPOS];
__device__ __nv_bfloat16 g_wh[3 * D_ * C_];
__device__ __nv_bfloat16 g_wl[3 * D_ * C_];
__device__ __nv_bfloat16 g_qh[(size_t)B_ * NPOS * D_];
__device__ __nv_bfloat16 g_ql[(size_t)B_ * NPOS * D_];
__device__ __nv_bfloat16 g_kh[(size_t)B_ * NPOS * D_];
__device__ __nv_bfloat16 g_kl[(size_t)B_ * NPOS * D_];
__device__ __nv_bfloat16 g_vth[(size_t)B_ * D_ * NPOS];  // V^T [b][d][n]
__device__ __nv_bfloat16 g_vtl[(size_t)B_ * D_ * NPOS];
__device__ float g_yp[NSPLIT][(size_t)B_ * NPOS * D_];   // unnormalized partial O
__device__ float g_lp[NSPLIT][(size_t)B_ * NPOS];        // partial l

// ======================= helpers ==================
__device__ __forceinline__ uint32_t smem_to_u32(const void* p) {
    uint32_t a;
    asm("{ .reg .u64 t; cvta.to.shared.u64 t, %1; cvt.u32.u64 %0, t; }" : "=r"(a) : "l"(p));
    return a;
}
__device__ __forceinline__ void cpa16(uint32_t s, const void* g) {
    asm volatile("cp.async.cg.shared.global [%0], [%1], 16;" :: "r"(s), "l"(g));
}
#define CP_COMMIT() asm volatile("cp.async.commit_group;" ::: "memory")

// D = A(16x16 bf16, row) * B(16x8 bf16, col) + D (f32)
#define MMA16816(c, a, b0_, b1_) \
    asm volatile("mma.sync.aligned.m16n8k16.row.col.f32.bf16.bf16.f32 " \
        "{%0,%1,%2,%3}, {%4,%5,%6,%7}, {%8,%9}, {%0,%1,%2,%3};" \
        : "+f"((c)[0]), "+f"((c)[1]), "+f"((c)[2]), "+f"((c)[3]) \
        : "r"((a)[0]), "r"((a)[1]), "r"((a)[2]), "r"((a)[3]), "r"(b0_), "r"(b1_))

#define LDMX4(rr, addr) \
    asm volatile("ldmatrix.sync.aligned.m8n8.x4.shared.b16 {%0,%1,%2,%3}, [%4];" \
        : "=r"((rr)[0]), "=r"((rr)[1]), "=r"((rr)[2]), "=r"((rr)[3]) : "r"(addr))
#define LDMX4T(rr, addr) \
    asm volatile("ldmatrix.sync.aligned.m8n8.x4.trans.shared.b16 {%0,%1,%2,%3}, [%4];" \
        : "=r"((rr)[0]), "=r"((rr)[1]), "=r"((rr)[2]), "=r"((rr)[3]) : "r"(addr))

// split f32 pair -> hi(trunc) packed bf16x2 (a in low half) + lo(rn) packed
__device__ __forceinline__ uint32_t packsplit(float a, float b, uint32_t& lo) {
    uint32_t ua = __float_as_uint(a), ub = __float_as_uint(b);
    float r0 = a - __uint_as_float(ua & 0xFFFF0000u);
    float r1 = b - __uint_as_float(ub & 0xFFFF0000u);
    asm("cvt.rn.bf16x2.f32 %0, %1, %2;" : "=r"(lo) : "f"(r1), "f"(r0));
    return (ua >> 16) | (ub & 0xFFFF0000u);
}

// =============================================================================
// Kernel 0a: split x -> bf16 hi/lo.  grid 6272, 256 thr (exact cover, float4).
// =============================================================================
__global__ void __launch_bounds__(256) split_x_kernel(const float* __restrict__ x)
{
    size_t i = ((size_t)blockIdx.x * 256 + threadIdx.x) * 4;
    float4 v = *(const float4*)(x + i);
    uint32_t l0, l1;
    uint32_t h0 = packsplit(v.x, v.y, l0);
    uint32_t h1 = packsplit(v.z, v.w, l1);
    *(uint2*)((uint16_t*)g_xh + i) = make_uint2(h0, h1);
    *(uint2*)((uint16_t*)g_xl + i) = make_uint2(l0, l1);
}

// Kernel 0b: split W{theta,phi,g} -> bf16 hi/lo.  grid (32, 3).
__global__ void __launch_bounds__(256) split_w_kernel(
    const float* __restrict__ Wt, const float* __restrict__ Wp,
    const float* __restrict__ Wg_)
{
    int which = blockIdx.y;
    const float* W = (which == 0) ? Wt : (which == 1) ? Wp : Wg_;
    size_t i = ((size_t)blockIdx.x * 256 + threadIdx.x) * 4;
    float4 v = *(const float4*)(W + i);
    uint32_t l0, l1;
    uint32_t h0 = packsplit(v.x, v.y, l0);
    uint32_t h1 = packsplit(v.z, v.w, l1);
    size_t o = (size_t)which * (D_ * C_) + i;
    *(uint2*)((uint16_t*)g_wh + o) = make_uint2(h0, h1);
    *(uint2*)((uint16_t*)g_wl + o) = make_uint2(l0, l1);
}

// =============================================================================
// Kernel 1: proj via mma.sync (3-pass bf16 emulation).
// grid (49, 3, B), 256 thr (8 warps).  which: 0=theta->Q, 1=phi->K, 2=g->V^T.
// =============================================================================
#define PSTG 37888
#define PROJ_SMEM (3 * PSTG)   // 113664

__device__ __forceinline__ void proj_ld(uint32_t sb, int s, int b, int which,
                                        int c0, int n0, int tid)
{
    uint32_t st = sb + (uint32_t)s * PSTG;
#pragma unroll
    for (int i = 0; i < 2; i++) {
        int ch = tid + i * 256;
        int r = ch >> 4, c16 = ch & 15;
        size_t src = ((size_t)(b * C_ + c0 + r)) * NPOS + n0 + c16 * 8;
        uint32_t dst = (uint32_t)(r * 272 + c16 * 16);
        cpa16(st + dst, (const char*)g_xh + src * 2);
        cpa16(st + 8704 + dst, (const char*)g_xl + src * 2);
    }
#pragma unroll
    for (int i = 0; i < 2; i++) {
        int ch = tid + i * 256;
        int r = ch >> 2, c16 = ch & 3;
        size_t src = (size_t)which * (D_ * C_) + (size_t)r * C_ + c0 + c16 * 8;
        uint32_t dst = (uint32_t)(r * 80 + c16 * 16);
        cpa16(st + 17408 + dst, (const char*)g_wh + src * 2);
        cpa16(st + 27648 + dst, (const char*)g_wl + src * 2);
    }
}

__global__ void __launch_bounds__(256) proj_mma_kernel()
{
    extern __shared__ char smem[];
    uint32_t sb = smem_to_u32(smem);
    const int tid = threadIdx.x;
    const int w = tid >> 5, lane = tid & 31;
    const int g = lane >> 2, tq = lane & 3;
    const int b = blockIdx.z, which = blockIdx.y;
    const int n0 = blockIdx.x * 128;

    proj_ld(sb, 0, b, which, 0, n0, tid);
    CP_COMMIT();
    proj_ld(sb, 1, b, which, 32, n0, tid);
    CP_COMMIT();

    float acc[16][4];
#pragma unroll
    for (int j = 0; j < 16; j++)
#pragma unroll
        for (int e = 0; e < 4; e++) acc[j][e] = 0.f;

    const int l7 = lane & 7, lb3 = (lane >> 3) & 1, lb4 = lane >> 4;
    const uint32_t laneAX = (uint32_t)((l7 + lb4 * 8) * 272 + (lb3 * 8) * 2);
    const uint32_t laneBW = (uint32_t)((lb4 * 8 + l7) * 80 + lb3 * 16);
    const uint32_t laneAW = (uint32_t)((l7 + lb3 * 8) * 80 + lb4 * 16);
    const uint32_t laneBX = (uint32_t)((l7 + lb3 * 8) * 272 + (lb4 * 8) * 2);

    int st = 0;
    for (int it = 0; it < 8; it++) {
        if (it + 1 < 8) {
            asm volatile("cp.async.wait_group 1;" ::: "memory");
        } else {
            asm volatile("cp.async.wait_group 0;" ::: "memory");
        }
        __syncthreads();
        if (it + 2 < 8) {
            proj_ld(sb, (st >= 1) ? st - 1 : st + 2, b, which, (it + 2) * 32, n0, tid);
            CP_COMMIT();
        }

        const uint32_t XH = sb + (uint32_t)st * PSTG;
        const uint32_t WH = XH + 17408;

        if (which < 2) {
#pragma unroll
            for (int kk = 0; kk < 2; kk++) {
                uint32_t axh[4], axl[4];
                uint32_t aaddr = XH + (uint32_t)(kk * 16 * 272) + (uint32_t)(w * 16 * 2) + laneAX;
                LDMX4T(axh, aaddr);
                LDMX4T(axl, aaddr + 8704);
#pragma unroll
                for (int jp = 0; jp < 8; jp++) {
                    uint32_t baddr = WH + (uint32_t)(jp * 16 * 80 + kk * 32) + laneBW;
                    uint32_t bh[4], bl[4];
                    LDMX4(bh, baddr);
                    LDMX4(bl, baddr + 10240);
                    MMA16816(acc[2 * jp],     axh, bh[0], bh[1]);
                    MMA16816(acc[2 * jp + 1], axh, bh[2], bh[3]);
                    MMA16816(acc[2 * jp],     axl, bh[0], bh[1]);
                    MMA16816(acc[2 * jp + 1], axl, bh[2], bh[3]);
                    MMA16816(acc[2 * jp],     axh, bl[0], bl[1]);
                    MMA16816(acc[2 * jp + 1], axh, bl[2], bl[3]);
                }
            }
        } else {
#pragma unroll
            for (int kk = 0; kk < 2; kk++) {
                uint32_t awh[4], awl[4];
                uint32_t aaddr = WH + (uint32_t)(w * 16 * 80 + kk * 32) + laneAW;
                LDMX4(awh, aaddr);
                LDMX4(awl, aaddr + 10240);
#pragma unroll
                for (int jp = 0; jp < 8; jp++) {
                    uint32_t baddr = XH + (uint32_t)(kk * 16 * 272) + (uint32_t)(jp * 16 * 2) + laneBX;
                    uint32_t bxh[4], bxl[4];
                    LDMX4T(bxh, baddr);
                    LDMX4T(bxl, baddr + 8704);
                    MMA16816(acc[2 * jp],     awh, bxh[0], bxh[1]);
                    MMA16816(acc[2 * jp + 1], awh, bxh[2], bxh[3]);
                    MMA16816(acc[2 * jp],     awl, bxh[0], bxh[1]);
                    MMA16816(acc[2 * jp + 1], awl, bxh[2], bxh[3]);
                    MMA16816(acc[2 * jp],     awh, bxl[0], bxl[1]);
                    MMA16816(acc[2 * jp + 1], awh, bxl[2], bxl[3]);
                }
            }
        }
        st = (st == 2) ? 0 : st + 1;
    }

    if (which < 2) {
        uint16_t* hi = (uint16_t*)((which == 0) ? g_qh : g_kh);
        uint16_t* lo = (uint16_t*)((which == 0) ? g_ql : g_kl);
        size_t row0 = ((size_t)b * NPOS + n0 + w * 16 + g) * D_;
        size_t row1 = row0 + (size_t)8 * D_;
#pragma unroll
        for (int j = 0; j < 16; j++) {
            int col = j * 8 + 2 * tq;
            uint32_t lo0, lo1;
            uint32_t h0 = packsplit(acc[j][0], acc[j][1], lo0);
            uint32_t h1 = packsplit(acc[j][2], acc[j][3], lo1);
            *(uint32_t*)(hi + row0 + col) = h0;
            *(uint32_t*)(lo + row0 + col) = lo0;
            *(uint32_t*)(hi + row1 + col) = h1;
            *(uint32_t*)(lo + row1 + col) = lo1;
        }
    } else {
        uint16_t* hi = (uint16_t*)g_vth;
        uint16_t* lo = (uint16_t*)g_vtl;
        size_t row0 = ((size_t)b * D_ + w * 16 + g) * NPOS + n0;
        size_t row1 = row0 + (size_t)8 * NPOS;
#pragma unroll
        for (int j = 0; j < 16; j++) {
            int col = j * 8 + 2 * tq;
            uint32_t lo0, lo1;
            uint32_t h0 = packsplit(acc[j][0], acc[j][1], lo0);
            uint32_t h1 = packsplit(acc[j][2], acc[j][3], lo1);
            *(uint32_t*)(hi + row0 + col) = h0;
            *(uint32_t*)(lo + row0 + col) = lo0;
            *(uint32_t*)(hi + row1 + col) = h1;
            *(uint32_t*)(lo + row1 + col) = lo1;
        }
    }
}

// =============================================================================
// Kernel 2: flash attention via mma.sync, jp-outer pipelined S/softmax/PV.
// grid (49, NSPLIT, B), 256 threads (8 warps x 16 q-rows), BM=128, BN=64.
// =============================================================================
#define SZ_KHL  17408
#define SZ_KST  (2 * SZ_KHL)             // 34816
#define OFF_V   (3 * SZ_KST)             // 104448
#define SZ_VHL  18432
#define SZ_VST  (2 * SZ_VHL)             // 36864
#define FLASH_SMEM (OFF_V + 3 * SZ_VST)  // 215040

__device__ __forceinline__ void ld_stage(uint32_t sb, int st, int b, int kt, int tid)
{
    const char* kh = (const char*)(g_kh + ((size_t)b * NPOS + (size_t)kt * BN) * D_);
    const char* kl = (const char*)(g_kl + ((size_t)b * NPOS + (size_t)kt * BN) * D_);
    uint32_t kb = sb + st * SZ_KST;
#pragma unroll
    for (int i = 0; i < 4; i++) {
        int ch = tid + i * 256;
        int r = ch >> 4, c = ch & 15;
        uint32_t off = (uint32_t)(r * 272 + c * 16);
        size_t go = (size_t)r * 256 + c * 16;
        cpa16(kb + off, kh + go);
        cpa16(kb + SZ_KHL + off, kl + go);
    }
    const char* vh = (const char*)(g_vth + (size_t)b * D_ * NPOS + (size_t)kt * BN);
    const char* vl = (const char*)(g_vtl + (size_t)b * D_ * NPOS + (size_t)kt * BN);
    uint32_t vb = sb + OFF_V + st * SZ_VST;
#pragma unroll
    for (int i = 0; i < 4; i++) {
        int ch = tid + i * 256;
        int r = ch >> 3, c = ch & 7;
        uint32_t off = (uint32_t)(r * 144 + c * 16);
        size_t go = (size_t)r * (NPOS * 2) + c * 16;
        cpa16(vb + off, vh + go);
        cpa16(vb + SZ_VHL + off, vl + go);
    }
}

__global__ void __launch_bounds__(256, 1) flash_kernel()
{
    extern __shared__ char smem[];
    uint32_t sb = smem_to_u32(smem);
    const int tid = threadIdx.x;
    const int w = tid >> 5, lane = tid & 31;
    const int g = lane >> 2, tq = lane & 3;
    const int q0 = blockIdx.x * 128;
    const int split = blockIdx.y;
    const int b = blockIdx.z;
    const int ks = (split * 98) / 3;
    const int ke = ((split + 1) * 98) / 3;

    ld_stage(sb, 0, b, ks, tid);
    CP_COMMIT();
    ld_stage(sb, 1, b, ks + 1, tid);
    CP_COMMIT();

    uint32_t qh[8][4], ql[8][4];
    {
        const uint16_t* gh = (const uint16_t*)(g_qh + ((size_t)b * NPOS + q0 + w * 16) * D_);
        const uint16_t* gl = (const uint16_t*)(g_ql + ((size_t)b * NPOS + q0 + w * 16) * D_);
#pragma unroll
        for (int kk = 0; kk < 8; kk++) {
            size_t o0 = (size_t)g * 128 + kk * 16 + 2 * tq;
            size_t o1 = (size_t)(g + 8) * 128 + kk * 16 + 2 * tq;
            qh[kk][0] = *(const uint32_t*)(gh + o0);
            qh[kk][1] = *(const uint32_t*)(gh + o1);
            qh[kk][2] = *(const uint32_t*)(gh + o0 + 8);
            qh[kk][3] = *(const uint32_t*)(gh + o1 + 8);
            ql[kk][0] = *(const uint32_t*)(gl + o0);
            ql[kk][1] = *(const uint32_t*)(gl + o1);
            ql[kk][2] = *(const uint32_t*)(gl + o0 + 8);
            ql[kk][3] = *(const uint32_t*)(gl + o1 + 8);
        }
    }

    float oacc[16][4];
#pragma unroll
    for (int j = 0; j < 16; j++)
#pragma unroll
        for (int e = 0; e < 4; e++) oacc[j][e] = 0.f;
    float lr0 = 0.f, lr1 = 0.f;

    const int r8 = lane & 7, half = (lane >> 3) & 1, jjo = lane >> 4;
    const uint32_t laneK = (uint32_t)((jjo * 8 + r8) * 272 + half * 16);
    const uint32_t laneV = (uint32_t)((jjo * 8 + r8) * 144 + half * 16);

    int st = 0;
    for (int t = ks; t < ke; t++) {
        if (t + 1 < ke) {
            asm volatile("cp.async.wait_group 1;" ::: "memory");
        } else {
            asm volatile("cp.async.wait_group 0;" ::: "memory");
        }
        __syncthreads();
        if (t + 2 < ke) {
            ld_stage(sb, (st >= 1) ? st - 1 : st + 2, b, t + 2, tid);
            CP_COMMIT();
        }

        const uint32_t Kh = sb + st * SZ_KST;
        const uint32_t Vh = sb + OFF_V + st * SZ_VST;

        // jp-outer: for each 16-col kv chunk, S -> softmax -> PV.  Straight-line
        // unrolled code lets the scheduler overlap softmax(jp) with S(jp+1) and
        // PV(jp) MMAs, keeping the tensor pipe fed.
#pragma unroll
        for (int jp = 0; jp < 4; jp++) {
            float s0[4] = {0.f, 0.f, 0.f, 0.f}, s1[4] = {0.f, 0.f, 0.f, 0.f};
#pragma unroll
            for (int kk = 0; kk < 8; kk++) {
                uint32_t addr = Kh + (uint32_t)(jp * (16 * 272) + kk * 32) + laneK;
                uint32_t bh[4], bl[4];
                LDMX4(bh, addr);
                LDMX4(bl, addr + SZ_KHL);
                MMA16816(s0, qh[kk], bh[0], bh[1]);
                MMA16816(s1, qh[kk], bh[2], bh[3]);
                MMA16816(s0, ql[kk], bh[0], bh[1]);
                MMA16816(s1, ql[kk], bh[2], bh[3]);
                MMA16816(s0, qh[kk], bl[0], bl[1]);
                MMA16816(s1, qh[kk], bl[2], bl[3]);
            }

            // softmax for this chunk's 16 columns
            uint32_t phj[4], plj[4];
            {
                float p0 = __expf(s0[0] - MFIX);
                float p1 = __expf(s0[1] - MFIX);
                float p2 = __expf(s0[2] - MFIX);
                float p3 = __expf(s0[3] - MFIX);
                lr0 += p0 + p1;
                lr1 += p2 + p3;
                phj[0] = packsplit(p0, p1, plj[0]);
                phj[1] = packsplit(p2, p3, plj[1]);
                float q0f = __expf(s1[0] - MFIX);
                float q1f = __expf(s1[1] - MFIX);
                float q2f = __expf(s1[2] - MFIX);
                float q3f = __expf(s1[3] - MFIX);
                lr0 += q0f + q1f;
                lr1 += q2f + q3f;
                phj[2] = packsplit(q0f, q1f, plj[2]);
                phj[3] = packsplit(q2f, q3f, plj[3]);
            }

            // PV for this kv chunk across all 8 d-groups
#pragma unroll
            for (int j2 = 0; j2 < 8; j2++) {
                uint32_t addr = Vh + (uint32_t)(j2 * (16 * 144) + jp * 32) + laneV;
                uint32_t vh_[4], vl_[4];
                LDMX4(vh_, addr);
                LDMX4(vl_, addr + SZ_VHL);
                MMA16816(oacc[2 * j2],     phj, vh_[0], vh_[1]);
                MMA16816(oacc[2 * j2 + 1], phj, vh_[2], vh_[3]);
                MMA16816(oacc[2 * j2],     plj, vh_[0], vh_[1]);
                MMA16816(oacc[2 * j2 + 1], plj, vh_[2], vh_[3]);
                MMA16816(oacc[2 * j2],     phj, vl_[0], vl_[1]);
                MMA16816(oacc[2 * j2 + 1], phj, vl_[2], vl_[3]);
            }
        }

        st = (st == 2) ? 0 : st + 1;
    }

    lr0 += __shfl_xor_sync(0xffffffffu, lr0, 1);
    lr0 += __shfl_xor_sync(0xffffffffu, lr0, 2);
    lr1 += __shfl_xor_sync(0xffffffffu, lr1, 1);
    lr1 += __shfl_xor_sync(0xffffffffu, lr1, 2);
    if (tq == 0) {
        size_t base = (size_t)b * NPOS + q0 + w * 16;
        g_lp[split][base + g] = lr0;
        g_lp[split][base + g + 8] = lr1;
    }

    float* yd = g_yp[split] + ((size_t)b * NPOS + q0 + w * 16) * D_;
#pragma unroll
    for (int j = 0; j < 16; j++) {
        *(float2*)(yd + (size_t)g * D_ + j * 8 + 2 * tq) = make_float2(oacc[j][0], oacc[j][1]);
        *(float2*)(yd + (size_t)(g + 8) * D_ + j * 8 + 2 * tq) = make_float2(oacc[j][2], oacc[j][3]);
    }
}

// =============================================================================
// Kernel 3 (mma): out[b][c][n] = x + Wz @ (Σ_s y_s / L).
// =============================================================================
#define EPI_WZH  0
#define EPI_WZL  34816
#define EPI_YH   69632
#define EPI_YL   87040
#define EPI_LINV 104448
#define EPI_SMEM (EPI_LINV + 256)

__global__ void __launch_bounds__(256) epi_kernel(
    const float* __restrict__ Wz, const float* __restrict__ x, float* __restrict__ out)
{
    extern __shared__ char smem[];
    uint32_t sb = smem_to_u32(smem);
    const int tid = threadIdx.x;
    const int w = tid >> 5, lane = tid & 31;
    const int g = lane >> 2, tq = lane & 3;
    const int b = blockIdx.z;
    const int c0 = blockIdx.y * 128;
    const int n0 = blockIdx.x * 64;

    float* linv = (float*)(smem + EPI_LINV);
    if (tid < 64) {
        size_t li = (size_t)b * NPOS + n0 + tid;
        linv[tid] = 1.f / (g_lp[0][li] + g_lp[1][li] + g_lp[2][li]);
    }
    __syncthreads();

    for (int v = tid; v < 128 * 32; v += 256) {
        int r = v >> 5, c = v & 31;
        float4 wv = *(const float4*)(Wz + (size_t)(c0 + r) * D_ + 4 * c);
        uint32_t l0, l1;
        uint32_t h0 = packsplit(wv.x, wv.y, l0);
        uint32_t h1 = packsplit(wv.z, wv.w, l1);
        *(uint2*)(smem + EPI_WZH + r * 272 + c * 8) = make_uint2(h0, h1);
        *(uint2*)(smem + EPI_WZL + r * 272 + c * 8) = make_uint2(l0, l1);
    }
    {
        const float* y0 = g_yp[0] + ((size_t)b * NPOS + n0) * D_;
        const float* y1 = g_yp[1] + ((size_t)b * NPOS + n0) * D_;
        const float* y2 = g_yp[2] + ((size_t)b * NPOS + n0) * D_;
        for (int v = tid; v < 64 * 32; v += 256) {
            int r = v >> 5, c = v & 31;
            size_t o = (size_t)r * D_ + 4 * c;
            float4 a = *(const float4*)(y0 + o);
            float4 bb = *(const float4*)(y1 + o);
            float4 cc = *(const float4*)(y2 + o);
            float s = linv[r];
            float vx = (a.x + bb.x + cc.x) * s;
            float vy = (a.y + bb.y + cc.y) * s;
            float vz = (a.z + bb.z + cc.z) * s;
            float vw = (a.w + bb.w + cc.w) * s;
            uint32_t l0, l1;
            uint32_t h0 = packsplit(vx, vy, l0);
            uint32_t h1 = packsplit(vz, vw, l1);
            *(uint2*)(smem + EPI_YH + r * 272 + c * 8) = make_uint2(h0, h1);
            *(uint2*)(smem + EPI_YL + r * 272 + c * 8) = make_uint2(l0, l1);
        }
    }
    __syncthreads();

    float acc[8][4];
#pragma unroll
    for (int j = 0; j < 8; j++)
#pragma unroll
        for (int e = 0; e < 4; e++) acc[j][e] = 0.f;

    const int r8 = lane & 7;
    const uint32_t laneA = (uint32_t)((((lane >> 3) & 1) * 8 + r8) * 272 + (lane >> 4) * 16);
    const uint32_t laneB = (uint32_t)(((lane >> 4) * 8 + r8) * 272 + ((lane >> 3) & 1) * 16);
    const uint32_t wA = sb + EPI_WZH + (uint32_t)(w * 16 * 272);

#pragma unroll
    for (int kk = 0; kk < 8; kk++) {
        uint32_t ah[4], al[4];
        LDMX4(ah, wA + kk * 32 + laneA);
        LDMX4(al, wA + (EPI_WZL - EPI_WZH) + kk * 32 + laneA);
#pragma unroll
        for (int jp = 0; jp < 4; jp++) {
            uint32_t ba = sb + EPI_YH + (uint32_t)(jp * (16 * 272) + kk * 32) + laneB;
            uint32_t bh[4], bl[4];
            LDMX4(bh, ba);
            LDMX4(bl, ba + (EPI_YL - EPI_YH));
            MMA16816(acc[2 * jp],     ah, bh[0], bh[1]);
            MMA16816(acc[2 * jp + 1], ah, bh[2], bh[3]);
            MMA16816(acc[2 * jp],     al, bh[0], bh[1]);
            MMA16816(acc[2 * jp + 1], al, bh[2], bh[3]);
            MMA16816(acc[2 * jp],     ah, bl[0], bl[1]);
            MMA16816(acc[2 * jp + 1], ah, bl[2], bl[3]);
        }
    }

    const size_t row0 = (size_t)(b * C_ + c0 + w * 16 + g) * NPOS + n0;
    const size_t row1 = row0 + (size_t)8 * NPOS;
#pragma unroll
    for (int j = 0; j < 8; j++) {
        int col = j * 8 + 2 * tq;
        float2 x0 = *(const float2*)(x + row0 + col);
        float2 x1 = *(const float2*)(x + row1 + col);
        *(float2*)(out + row0 + col) = make_float2(acc[j][0] + x0.x, acc[j][1] + x0.y);
        *(float2*)(out + row1 + col) = make_float2(acc[j][2] + x1.x, acc[j][3] + x1.y);
    }
}

// =============================================================================
extern "C" void kernel_launch(void* const* d_in, const int* in_sizes, int n_in,
                              void* d_out, int out_size)
{
    const float* x      = (const float*)d_in[0];
    const float* Wg     = (const float*)d_in[1];
    const float* Wtheta = (const float*)d_in[2];
    const float* Wphi   = (const float*)d_in[3];
    const float* Wz     = (const float*)d_in[4];
    float* out = (float*)d_out;

    cudaFuncSetAttribute(proj_mma_kernel, cudaFuncAttributeMaxDynamicSharedMemorySize, PROJ_SMEM);
    cudaFuncSetAttribute(flash_kernel, cudaFuncAttributeMaxDynamicSharedMemorySize, FLASH_SMEM);
    cudaFuncSetAttribute(epi_kernel, cudaFuncAttributeMaxDynamicSharedMemorySize, EPI_SMEM);

    split_x_kernel<<<6272, 256>>>(x);
    split_w_kernel<<<dim3(32, 3), 256>>>(Wtheta, Wphi, Wg);
    proj_mma_kernel<<<dim3(NPOS / 128, 3, B_), 256, PROJ_SMEM>>>();
    flash_kernel<<<dim3(NPOS / 128, NSPLIT, B_), 256, FLASH_SMEM>>>();
    epi_kernel<<<dim3(NPOS / 64, C_ / 128, B_), 256, EPI_SMEM>>>(Wz, x, out);
}

// round 9
// speedup vs baseline: 4.3645x; 1.0016x over previous
#include <cuda_runtime.h>
#include <cuda_bf16.h>
#include <cstdint>
#include <math.h>

#define B_    4
#define C_    256
#define D_    128
#define NPOS  6272
#define BN    64
#define NSPLIT 3
#define MFIX  80.0f

// ---------------- scratch (static __device__, no allocation) ----------------
__device__ __nv_bfloat16 g_xh[(size_t)B_ * C_ * NPOS];
__device__ __nv_bfloat16 g_xl[(size_t)B_ * C_ * NPOS];
__device__ __nv_bfloat16 g_wh[3 * D_ * C_];
__device__ __nv_bfloat16 g_wl[3 * D_ * C_];
__device__ __nv_bfloat16 g_qh[(size_t)B_ * NPOS * D_];
__device__ __nv_bfloat16 g_ql[(size_t)B_ * NPOS * D_];
__device__ __nv_bfloat16 g_kh[(size_t)B_ * NPOS * D_];
__device__ __nv_bfloat16 g_kl[(size_t)B_ * NPOS * D_];
__device__ __nv_bfloat16 g_vth[(size_t)B_ * D_ * NPOS];  // V^T [b][d][n]
__device__ __nv_bfloat16 g_vtl[(size_t)B_ * D_ * NPOS];
__device__ float g_yp[NSPLIT][(size_t)B_ * NPOS * D_];   // unnormalized partial O
__device__ float g_lp[NSPLIT][(size_t)B_ * NPOS];        // partial l

// ======================= helpers ==================
__device__ __forceinline__ uint32_t smem_to_u32(const void* p) {
    uint32_t a;
    asm("{ .reg .u64 t; cvta.to.shared.u64 t, %1; cvt.u32.u64 %0, t; }" : "=r"(a) : "l"(p));
    return a;
}
__device__ __forceinline__ void cpa16(uint32_t s, const void* g) {
    asm volatile("cp.async.cg.shared.global [%0], [%1], 16;" :: "r"(s), "l"(g));
}
#define CP_COMMIT() asm volatile("cp.async.commit_group;" ::: "memory")

// D = A(16x16 bf16, row) * B(16x8 bf16, col) + D (f32)
#define MMA16816(c, a, b0_, b1_) \
    asm volatile("mma.sync.aligned.m16n8k16.row.col.f32.bf16.bf16.f32 " \
        "{%0,%1,%2,%3}, {%4,%5,%6,%7}, {%8,%9}, {%0,%1,%2,%3};" \
        : "+f"((c)[0]), "+f"((c)[1]), "+f"((c)[2]), "+f"((c)[3]) \
        : "r"((a)[0]), "r"((a)[1]), "r"((a)[2]), "r"((a)[3]), "r"(b0_), "r"(b1_))

#define LDMX4(rr, addr) \
    asm volatile("ldmatrix.sync.aligned.m8n8.x4.shared.b16 {%0,%1,%2,%3}, [%4];" \
        : "=r"((rr)[0]), "=r"((rr)[1]), "=r"((rr)[2]), "=r"((rr)[3]) : "r"(addr))
#define LDMX4T(rr, addr) \
    asm volatile("ldmatrix.sync.aligned.m8n8.x4.trans.shared.b16 {%0,%1,%2,%3}, [%4];" \
        : "=r"((rr)[0]), "=r"((rr)[1]), "=r"((rr)[2]), "=r"((rr)[3]) : "r"(addr))

// split f32 pair -> hi(trunc) packed bf16x2 (a in low half) + lo(rn) packed
__device__ __forceinline__ uint32_t packsplit(float a, float b, uint32_t& lo) {
    uint32_t ua = __float_as_uint(a), ub = __float_as_uint(b);
    float r0 = a - __uint_as_float(ua & 0xFFFF0000u);
    float r1 = b - __uint_as_float(ub & 0xFFFF0000u);
    asm("cvt.rn.bf16x2.f32 %0, %1, %2;" : "=r"(lo) : "f"(r1), "f"(r0));
    return (ua >> 16) | (ub & 0xFFFF0000u);
}

// =============================================================================
// Kernel 0a: split x -> bf16 hi/lo.
// =============================================================================
__global__ void __launch_bounds__(256) split_x_kernel(const float* __restrict__ x)
{
    size_t i = ((size_t)blockIdx.x * 256 + threadIdx.x) * 4;
    float4 v = *(const float4*)(x + i);
    uint32_t l0, l1;
    uint32_t h0 = packsplit(v.x, v.y, l0);
    uint32_t h1 = packsplit(v.z, v.w, l1);
    *(uint2*)((uint16_t*)g_xh + i) = make_uint2(h0, h1);
    *(uint2*)((uint16_t*)g_xl + i) = make_uint2(l0, l1);
}

// Kernel 0b: split W{theta,phi,g} -> bf16 hi/lo.
__global__ void __launch_bounds__(256) split_w_kernel(
    const float* __restrict__ Wt, const float* __restrict__ Wp,
    const float* __restrict__ Wg_)
{
    int which = blockIdx.y;
    const float* W = (which == 0) ? Wt : (which == 1) ? Wp : Wg_;
    size_t i = ((size_t)blockIdx.x * 256 + threadIdx.x) * 4;
    float4 v = *(const float4*)(W + i);
    uint32_t l0, l1;
    uint32_t h0 = packsplit(v.x, v.y, l0);
    uint32_t h1 = packsplit(v.z, v.w, l1);
    size_t o = (size_t)which * (D_ * C_) + i;
    *(uint2*)((uint16_t*)g_wh + o) = make_uint2(h0, h1);
    *(uint2*)((uint16_t*)g_wl + o) = make_uint2(l0, l1);
}

// =============================================================================
// Kernel 1: proj via mma.sync (3-pass bf16 emulation). (unchanged, proven)
// =============================================================================
#define PSTG 37888
#define PROJ_SMEM (3 * PSTG)

__device__ __forceinline__ void proj_ld(uint32_t sb, int s, int b, int which,
                                        int c0, int n0, int tid)
{
    uint32_t st = sb + (uint32_t)s * PSTG;
#pragma unroll
    for (int i = 0; i < 2; i++) {
        int ch = tid + i * 256;
        int r = ch >> 4, c16 = ch & 15;
        size_t src = ((size_t)(b * C_ + c0 + r)) * NPOS + n0 + c16 * 8;
        uint32_t dst = (uint32_t)(r * 272 + c16 * 16);
        cpa16(st + dst, (const char*)g_xh + src * 2);
        cpa16(st + 8704 + dst, (const char*)g_xl + src * 2);
    }
#pragma unroll
    for (int i = 0; i < 2; i++) {
        int ch = tid + i * 256;
        int r = ch >> 2, c16 = ch & 3;
        size_t src = (size_t)which * (D_ * C_) + (size_t)r * C_ + c0 + c16 * 8;
        uint32_t dst = (uint32_t)(r * 80 + c16 * 16);
        cpa16(st + 17408 + dst, (const char*)g_wh + src * 2);
        cpa16(st + 27648 + dst, (const char*)g_wl + src * 2);
    }
}

__global__ void __launch_bounds__(256) proj_mma_kernel()
{
    extern __shared__ char smem[];
    uint32_t sb = smem_to_u32(smem);
    const int tid = threadIdx.x;
    const int w = tid >> 5, lane = tid & 31;
    const int g = lane >> 2, tq = lane & 3;
    const int b = blockIdx.z, which = blockIdx.y;
    const int n0 = blockIdx.x * 128;

    proj_ld(sb, 0, b, which, 0, n0, tid);
    CP_COMMIT();
    proj_ld(sb, 1, b, which, 32, n0, tid);
    CP_COMMIT();

    float acc[16][4];
#pragma unroll
    for (int j = 0; j < 16; j++)
#pragma unroll
        for (int e = 0; e < 4; e++) acc[j][e] = 0.f;

    const int l7 = lane & 7, lb3 = (lane >> 3) & 1, lb4 = lane >> 4;
    const uint32_t laneAX = (uint32_t)((l7 + lb4 * 8) * 272 + (lb3 * 8) * 2);
    const uint32_t laneBW = (uint32_t)((lb4 * 8 + l7) * 80 + lb3 * 16);
    const uint32_t laneAW = (uint32_t)((l7 + lb3 * 8) * 80 + lb4 * 16);
    const uint32_t laneBX = (uint32_t)((l7 + lb3 * 8) * 272 + (lb4 * 8) * 2);

    int st = 0;
    for (int it = 0; it < 8; it++) {
        if (it + 1 < 8) {
            asm volatile("cp.async.wait_group 1;" ::: "memory");
        } else {
            asm volatile("cp.async.wait_group 0;" ::: "memory");
        }
        __syncthreads();
        if (it + 2 < 8) {
            proj_ld(sb, (st >= 1) ? st - 1 : st + 2, b, which, (it + 2) * 32, n0, tid);
            CP_COMMIT();
        }

        const uint32_t XH = sb + (uint32_t)st * PSTG;
        const uint32_t WH = XH + 17408;

        if (which < 2) {
#pragma unroll
            for (int kk = 0; kk < 2; kk++) {
                uint32_t axh[4], axl[4];
                uint32_t aaddr = XH + (uint32_t)(kk * 16 * 272) + (uint32_t)(w * 16 * 2) + laneAX;
                LDMX4T(axh, aaddr);
                LDMX4T(axl, aaddr + 8704);
#pragma unroll
                for (int jp = 0; jp < 8; jp++) {
                    uint32_t baddr = WH + (uint32_t)(jp * 16 * 80 + kk * 32) + laneBW;
                    uint32_t bh[4], bl[4];
                    LDMX4(bh, baddr);
                    LDMX4(bl, baddr + 10240);
                    MMA16816(acc[2 * jp],     axh, bh[0], bh[1]);
                    MMA16816(acc[2 * jp + 1], axh, bh[2], bh[3]);
                    MMA16816(acc[2 * jp],     axl, bh[0], bh[1]);
                    MMA16816(acc[2 * jp + 1], axl, bh[2], bh[3]);
                    MMA16816(acc[2 * jp],     axh, bl[0], bl[1]);
                    MMA16816(acc[2 * jp + 1], axh, bl[2], bl[3]);
                }
            }
        } else {
#pragma unroll
            for (int kk = 0; kk < 2; kk++) {
                uint32_t awh[4], awl[4];
                uint32_t aaddr = WH + (uint32_t)(w * 16 * 80 + kk * 32) + laneAW;
                LDMX4(awh, aaddr);
                LDMX4(awl, aaddr + 10240);
#pragma unroll
                for (int jp = 0; jp < 8; jp++) {
                    uint32_t baddr = XH + (uint32_t)(kk * 16 * 272) + (uint32_t)(jp * 16 * 2) + laneBX;
                    uint32_t bxh[4], bxl[4];
                    LDMX4T(bxh, baddr);
                    LDMX4T(bxl, baddr + 8704);
                    MMA16816(acc[2 * jp],     awh, bxh[0], bxh[1]);
                    MMA16816(acc[2 * jp + 1], awh, bxh[2], bxh[3]);
                    MMA16816(acc[2 * jp],     awl, bxh[0], bxh[1]);
                    MMA16816(acc[2 * jp + 1], awl, bxh[2], bxh[3]);
                    MMA16816(acc[2 * jp],     awh, bxl[0], bxl[1]);
                    MMA16816(acc[2 * jp + 1], awh, bxl[2], bxl[3]);
                }
            }
        }
        st = (st == 2) ? 0 : st + 1;
    }

    if (which < 2) {
        uint16_t* hi = (uint16_t*)((which == 0) ? g_qh : g_kh);
        uint16_t* lo = (uint16_t*)((which == 0) ? g_ql : g_kl);
        size_t row0 = ((size_t)b * NPOS + n0 + w * 16 + g) * D_;
        size_t row1 = row0 + (size_t)8 * D_;
#pragma unroll
        for (int j = 0; j < 16; j++) {
            int col = j * 8 + 2 * tq;
            uint32_t lo0, lo1;
            uint32_t h0 = packsplit(acc[j][0], acc[j][1], lo0);
            uint32_t h1 = packsplit(acc[j][2], acc[j][3], lo1);
            *(uint32_t*)(hi + row0 + col) = h0;
            *(uint32_t*)(lo + row0 + col) = lo0;
            *(uint32_t*)(hi + row1 + col) = h1;
            *(uint32_t*)(lo + row1 + col) = lo1;
        }
    } else {
        uint16_t* hi = (uint16_t*)g_vth;
        uint16_t* lo = (uint16_t*)g_vtl;
        size_t row0 = ((size_t)b * D_ + w * 16 + g) * NPOS + n0;
        size_t row1 = row0 + (size_t)8 * NPOS;
#pragma unroll
        for (int j = 0; j < 16; j++) {
            int col = j * 8 + 2 * tq;
            uint32_t lo0, lo1;
            uint32_t h0 = packsplit(acc[j][0], acc[j][1], lo0);
            uint32_t h1 = packsplit(acc[j][2], acc[j][3], lo1);
            *(uint32_t*)(hi + row0 + col) = h0;
            *(uint32_t*)(lo + row0 + col) = lo0;
            *(uint32_t*)(hi + row1 + col) = h1;
            *(uint32_t*)(lo + row1 + col) = lo1;
        }
    }
}

// =============================================================================
// Kernel 2: flash attention.  Q hi/lo in SMEM (frees 64 regs), 2-stage K/V,
// explicit S(pairA) -> S(pairB) -> {softmax+PV}x4 software pipeline so the
// tensor pipe stays fed through softmax.
// SMEM: QH 34816 | QL 34816 | 2 x stage{KH,KL,VH,VL} 71680  = 212992 B
// =============================================================================
#define SZ_Q    34816
#define OFF_KV  (2 * SZ_Q)
#define SZ_KHL  17408
#define SZ_KST  (2 * SZ_KHL)
#define SZ_VHL  18432
#define SZ_VST  (2 * SZ_VHL)
#define SZ_STAGE (SZ_KST + SZ_VST)
#define FLASH_SMEM (OFF_KV + 2 * SZ_STAGE)   // 212992

__device__ __forceinline__ void ld_stage(uint32_t sb, int st, int b, int kt, int tid)
{
    const char* kh = (const char*)(g_kh + ((size_t)b * NPOS + (size_t)kt * BN) * D_);
    const char* kl = (const char*)(g_kl + ((size_t)b * NPOS + (size_t)kt * BN) * D_);
    uint32_t kb = sb + OFF_KV + st * SZ_STAGE;
#pragma unroll
    for (int i = 0; i < 4; i++) {
        int ch = tid + i * 256;
        int r = ch >> 4, c = ch & 15;
        uint32_t off = (uint32_t)(r * 272 + c * 16);
        size_t go = (size_t)r * 256 + c * 16;
        cpa16(kb + off, kh + go);
        cpa16(kb + SZ_KHL + off, kl + go);
    }
    const char* vh = (const char*)(g_vth + (size_t)b * D_ * NPOS + (size_t)kt * BN);
    const char* vl = (const char*)(g_vtl + (size_t)b * D_ * NPOS + (size_t)kt * BN);
    uint32_t vb = kb + SZ_KST;
#pragma unroll
    for (int i = 0; i < 4; i++) {
        int ch = tid + i * 256;
        int r = ch >> 3, c = ch & 7;
        uint32_t off = (uint32_t)(r * 144 + c * 16);
        size_t go = (size_t)r * (NPOS * 2) + c * 16;
        cpa16(vb + off, vh + go);
        cpa16(vb + SZ_VHL + off, vl + go);
    }
}

// S for one chunk-pair p (kv cols 32p .. 32p+31): Q frags from smem.
__device__ __forceinline__ void s_pair(float (&s)[2][2][4], uint32_t Kst, int p,
                                       uint32_t qbase, uint32_t laneK)
{
#pragma unroll
    for (int jc = 0; jc < 2; jc++)
#pragma unroll
        for (int h = 0; h < 2; h++)
#pragma unroll
            for (int e = 0; e < 4; e++) s[jc][h][e] = 0.f;
#pragma unroll
    for (int kk = 0; kk < 8; kk++) {
        uint32_t qh[4], ql[4];
        LDMX4(qh, qbase + kk * 32);
        LDMX4(ql, qbase + kk * 32 + SZ_Q);
#pragma unroll
        for (int jc = 0; jc < 2; jc++) {
            int jp = 2 * p + jc;
            uint32_t addr = Kst + (uint32_t)(jp * (16 * 272) + kk * 32) + laneK;
            uint32_t bh[4], bl[4];
            LDMX4(bh, addr);
            LDMX4(bl, addr + SZ_KHL);
            MMA16816(s[jc][0], qh, bh[0], bh[1]);
            MMA16816(s[jc][1], qh, bh[2], bh[3]);
            MMA16816(s[jc][0], ql, bh[0], bh[1]);
            MMA16816(s[jc][1], ql, bh[2], bh[3]);
            MMA16816(s[jc][0], qh, bl[0], bl[1]);
            MMA16816(s[jc][1], qh, bl[2], bl[3]);
        }
    }
}

// softmax of one 16-col chunk + its PV MMAs
__device__ __forceinline__ void sm_pv(const float (&sc)[2][4], int jp,
                                      uint32_t Vst, uint32_t laneV,
                                      float (&oacc)[16][4], float& lr0, float& lr1)
{
    uint32_t phj[4], plj[4];
    {
        float p0 = __expf(sc[0][0] - MFIX), p1 = __expf(sc[0][1] - MFIX);
        float p2 = __expf(sc[0][2] - MFIX), p3 = __expf(sc[0][3] - MFIX);
        lr0 += p0 + p1; lr1 += p2 + p3;
        phj[0] = packsplit(p0, p1, plj[0]);
        phj[1] = packsplit(p2, p3, plj[1]);
        float q0 = __expf(sc[1][0] - MFIX), q1 = __expf(sc[1][1] - MFIX);
        float q2 = __expf(sc[1][2] - MFIX), q3 = __expf(sc[1][3] - MFIX);
        lr0 += q0 + q1; lr1 += q2 + q3;
        phj[2] = packsplit(q0, q1, plj[2]);
        phj[3] = packsplit(q2, q3, plj[3]);
    }
#pragma unroll
    for (int j2 = 0; j2 < 8; j2++) {
        uint32_t addr = Vst + (uint32_t)(j2 * (16 * 144) + jp * 32) + laneV;
        uint32_t vh_[4], vl_[4];
        LDMX4(vh_, addr);
        LDMX4(vl_, addr + SZ_VHL);
        MMA16816(oacc[2 * j2],     phj, vh_[0], vh_[1]);
        MMA16816(oacc[2 * j2 + 1], phj, vh_[2], vh_[3]);
        MMA16816(oacc[2 * j2],     plj, vh_[0], vh_[1]);
        MMA16816(oacc[2 * j2 + 1], plj, vh_[2], vh_[3]);
        MMA16816(oacc[2 * j2],     phj, vl_[0], vl_[1]);
        MMA16816(oacc[2 * j2 + 1], phj, vl_[2], vl_[3]);
    }
}

__global__ void __launch_bounds__(256, 1) flash_kernel()
{
    extern __shared__ char smem[];
    uint32_t sb = smem_to_u32(smem);
    const int tid = threadIdx.x;
    const int w = tid >> 5, lane = tid & 31;
    const int g = lane >> 2, tq = lane & 3;
    const int q0 = blockIdx.x * 128;
    const int split = blockIdx.y;
    const int b = blockIdx.z;
    const int ks = (split * 98) / 3;
    const int ke = ((split + 1) * 98) / 3;

    // prologue: Q (hi/lo) + stage0 in group0; stage1 in group1
    {
        const char* gqh = (const char*)(g_qh + ((size_t)b * NPOS + q0) * D_);
        const char* gql = (const char*)(g_ql + ((size_t)b * NPOS + q0) * D_);
#pragma unroll
        for (int i = 0; i < 8; i++) {
            int ch = tid + i * 256;
            int r = ch >> 4, c = ch & 15;
            uint32_t dst = (uint32_t)(r * 272 + c * 16);
            size_t src = (size_t)r * 256 + c * 16;
            cpa16(sb + dst, gqh + src);
            cpa16(sb + SZ_Q + dst, gql + src);
        }
    }
    ld_stage(sb, 0, b, ks, tid);
    CP_COMMIT();
    ld_stage(sb, 1, b, ks + 1, tid);
    CP_COMMIT();

    float oacc[16][4];
#pragma unroll
    for (int j = 0; j < 16; j++)
#pragma unroll
        for (int e = 0; e < 4; e++) oacc[j][e] = 0.f;
    float lr0 = 0.f, lr1 = 0.f;

    const int r8 = lane & 7, half = (lane >> 3) & 1, jjo = lane >> 4;
    const uint32_t laneK = (uint32_t)((jjo * 8 + r8) * 272 + half * 16);
    const uint32_t laneV = (uint32_t)((jjo * 8 + r8) * 144 + half * 16);
    // Q A-fragment base: rows w*16 + half*8 + r8, k-halves selected by jjo
    const uint32_t qbase = sb + (uint32_t)((w * 16 + half * 8 + r8) * 272 + jjo * 16);

    int st = 0;
    for (int t = ks; t < ke; t++) {
        if (t + 1 < ke) {
            asm volatile("cp.async.wait_group 1;" ::: "memory");
        } else {
            asm volatile("cp.async.wait_group 0;" ::: "memory");
        }
        __syncthreads();

        const uint32_t Kst = sb + OFF_KV + st * SZ_STAGE;
        const uint32_t Vst = Kst + SZ_KST;

        float sA[2][2][4], sB[2][2][4];
        s_pair(sA, Kst, 0, qbase, laneK);
        s_pair(sB, Kst, 1, qbase, laneK);
        sm_pv(sA[0], 0, Vst, laneV, oacc, lr0, lr1);
        sm_pv(sA[1], 1, Vst, laneV, oacc, lr0, lr1);
        sm_pv(sB[0], 2, Vst, laneV, oacc, lr0, lr1);
        sm_pv(sB[1], 3, Vst, laneV, oacc, lr0, lr1);

        __syncthreads();
        if (t + 2 < ke) {
            ld_stage(sb, st, b, t + 2, tid);
            CP_COMMIT();
        }
        st ^= 1;
    }

    lr0 += __shfl_xor_sync(0xffffffffu, lr0, 1);
    lr0 += __shfl_xor_sync(0xffffffffu, lr0, 2);
    lr1 += __shfl_xor_sync(0xffffffffu, lr1, 1);
    lr1 += __shfl_xor_sync(0xffffffffu, lr1, 2);
    if (tq == 0) {
        size_t base = (size_t)b * NPOS + q0 + w * 16;
        g_lp[split][base + g] = lr0;
        g_lp[split][base + g + 8] = lr1;
    }

    float* yd = g_yp[split] + ((size_t)b * NPOS + q0 + w * 16) * D_;
#pragma unroll
    for (int j = 0; j < 16; j++) {
        *(float2*)(yd + (size_t)g * D_ + j * 8 + 2 * tq) = make_float2(oacc[j][0], oacc[j][1]);
        *(float2*)(yd + (size_t)(g + 8) * D_ + j * 8 + 2 * tq) = make_float2(oacc[j][2], oacc[j][3]);
    }
}

// =============================================================================
// Kernel 3 (mma): out[b][c][n] = x + Wz @ (Σ_s y_s / L).  (unchanged)
// =============================================================================
#define EPI_WZH  0
#define EPI_WZL  34816
#define EPI_YH   69632
#define EPI_YL   87040
#define EPI_LINV 104448
#define EPI_SMEM (EPI_LINV + 256)

__global__ void __launch_bounds__(256) epi_kernel(
    const float* __restrict__ Wz, const float* __restrict__ x, float* __restrict__ out)
{
    extern __shared__ char smem[];
    uint32_t sb = smem_to_u32(smem);
    const int tid = threadIdx.x;
    const int w = tid >> 5, lane = tid & 31;
    const int g = lane >> 2, tq = lane & 3;
    const int b = blockIdx.z;
    const int c0 = blockIdx.y * 128;
    const int n0 = blockIdx.x * 64;

    float* linv = (float*)(smem + EPI_LINV);
    if (tid < 64) {
        size_t li = (size_t)b * NPOS + n0 + tid;
        linv[tid] = 1.f / (g_lp[0][li] + g_lp[1][li] + g_lp[2][li]);
    }
    __syncthreads();

    for (int v = tid; v < 128 * 32; v += 256) {
        int r = v >> 5, c = v & 31;
        float4 wv = *(const float4*)(Wz + (size_t)(c0 + r) * D_ + 4 * c);
        uint32_t l0, l1;
        uint32_t h0 = packsplit(wv.x, wv.y, l0);
        uint32_t h1 = packsplit(wv.z, wv.w, l1);
        *(uint2*)(smem + EPI_WZH + r * 272 + c * 8) = make_uint2(h0, h1);
        *(uint2*)(smem + EPI_WZL + r * 272 + c * 8) = make_uint2(l0, l1);
    }
    {
        const float* y0 = g_yp[0] + ((size_t)b * NPOS + n0) * D_;
        const float* y1 = g_yp[1] + ((size_t)b * NPOS + n0) * D_;
        const float* y2 = g_yp[2] + ((size_t)b * NPOS + n0) * D_;
        for (int v = tid; v < 64 * 32; v += 256) {
            int r = v >> 5, c = v & 31;
            size_t o = (size_t)r * D_ + 4 * c;
            float4 a = *(const float4*)(y0 + o);
            float4 bb = *(const float4*)(y1 + o);
            float4 cc = *(const float4*)(y2 + o);
            float s = linv[r];
            float vx = (a.x + bb.x + cc.x) * s;
            float vy = (a.y + bb.y + cc.y) * s;
            float vz = (a.z + bb.z + cc.z) * s;
            float vw = (a.w + bb.w + cc.w) * s;
            uint32_t l0, l1;
            uint32_t h0 = packsplit(vx, vy, l0);
            uint32_t h1 = packsplit(vz, vw, l1);
            *(uint2*)(smem + EPI_YH + r * 272 + c * 8) = make_uint2(h0, h1);
            *(uint2*)(smem + EPI_YL + r * 272 + c * 8) = make_uint2(l0, l1);
        }
    }
    __syncthreads();

    float acc[8][4];
#pragma unroll
    for (int j = 0; j < 8; j++)
#pragma unroll
        for (int e = 0; e < 4; e++) acc[j][e] = 0.f;

    const int r8 = lane & 7;
    const uint32_t laneA = (uint32_t)((((lane >> 3) & 1) * 8 + r8) * 272 + (lane >> 4) * 16);
    const uint32_t laneB = (uint32_t)(((lane >> 4) * 8 + r8) * 272 + ((lane >> 3) & 1) * 16);
    const uint32_t wA = sb + EPI_WZH + (uint32_t)(w * 16 * 272);

#pragma unroll
    for (int kk = 0; kk < 8; kk++) {
        uint32_t ah[4], al[4];
        LDMX4(ah, wA + kk * 32 + laneA);
        LDMX4(al, wA + (EPI_WZL - EPI_WZH) + kk * 32 + laneA);
#pragma unroll
        for (int jp = 0; jp < 4; jp++) {
            uint32_t ba = sb + EPI_YH + (uint32_t)(jp * (16 * 272) + kk * 32) + laneB;
            uint32_t bh[4], bl[4];
            LDMX4(bh, ba);
            LDMX4(bl, ba + (EPI_YL - EPI_YH));
            MMA16816(acc[2 * jp],     ah, bh[0], bh[1]);
            MMA16816(acc[2 * jp + 1], ah, bh[2], bh[3]);
            MMA16816(acc[2 * jp],     al, bh[0], bh[1]);
            MMA16816(acc[2 * jp + 1], al, bh[2], bh[3]);
            MMA16816(acc[2 * jp],     ah, bl[0], bl[1]);
            MMA16816(acc[2 * jp + 1], ah, bl[2], bl[3]);
        }
    }

    const size_t row0 = (size_t)(b * C_ + c0 + w * 16 + g) * NPOS + n0;
    const size_t row1 = row0 + (size_t)8 * NPOS;
#pragma unroll
    for (int j = 0; j < 8; j++) {
        int col = j * 8 + 2 * tq;
        float2 x0 = *(const float2*)(x + row0 + col);
        float2 x1 = *(const float2*)(x + row1 + col);
        *(float2*)(out + row0 + col) = make_float2(acc[j][0] + x0.x, acc[j][1] + x0.y);
        *(float2*)(out + row1 + col) = make_float2(acc[j][2] + x1.x, acc[j][3] + x1.y);
    }
}

// =============================================================================
extern "C" void kernel_launch(void* const* d_in, const int* in_sizes, int n_in,
                              void* d_out, int out_size)
{
    const float* x      = (const float*)d_in[0];
    const float* Wg     = (const float*)d_in[1];
    const float* Wtheta = (const float*)d_in[2];
    const float* Wphi   = (const float*)d_in[3];
    const float* Wz     = (const float*)d_in[4];
    float* out = (float*)d_out;

    cudaFuncSetAttribute(proj_mma_kernel, cudaFuncAttributeMaxDynamicSharedMemorySize, PROJ_SMEM);
    cudaFuncSetAttribute(flash_kernel, cudaFuncAttributeMaxDynamicSharedMemorySize, FLASH_SMEM);
    cudaFuncSetAttribute(epi_kernel, cudaFuncAttributeMaxDynamicSharedMemorySize, EPI_SMEM);

    split_x_kernel<<<6272, 256>>>(x);
    split_w_kernel<<<dim3(32, 3), 256>>>(Wtheta, Wphi, Wg);
    proj_mma_kernel<<<dim3(NPOS / 128, 3, B_), 256, PROJ_SMEM>>>();
    flash_kernel<<<dim3(NPOS / 128, NSPLIT, B_), 256, FLASH_SMEM>>>();
    epi_kernel<<<dim3(NPOS / 64, C_ / 128, B_), 256, EPI_SMEM>>>(Wz, x, out);
}